// round 3
// baseline (speedup 1.0000x reference)
#include <cuda_runtime.h>
#include <math.h>

#define N_NODES 100000
#define IN_FEAT 128
#define HIDDEN 256
#define KTOT (2*IN_FEAT)   // concat [agg | x] -> K=256 for layer-1 GEMM

// ---- scratch (static device globals; no allocation allowed) ----
__device__ float g_agg1[(size_t)N_NODES * IN_FEAT];   // 51.2 MB
__device__ float g_cnt [N_NODES];
__device__ float g_inv [N_NODES];
__device__ float g_h1  [(size_t)N_NODES * HIDDEN];    // 102.4 MB
__device__ float g_agg2[(size_t)N_NODES * HIDDEN];    // 102.4 MB
__device__ float g_W1t [KTOT * HIDDEN];               // W1t[k][h] = k<128 ? W1_l[h][k] : W1_r[h][k-128]

// ---- zero scratch (graph-capturable replacement for cudaMemsetAsync) ----
__global__ void k_zero() {
    const size_t n1 = (size_t)N_NODES * IN_FEAT;   // g_agg1
    const size_t n2 = (size_t)N_NODES * HIDDEN;    // g_agg2
    size_t stride = (size_t)gridDim.x * blockDim.x;
    size_t i0 = (size_t)blockIdx.x * blockDim.x + threadIdx.x;
    float4 z = make_float4(0.f, 0.f, 0.f, 0.f);
    for (size_t i = i0; i < n1 / 4; i += stride) ((float4*)g_agg1)[i] = z;
    for (size_t i = i0; i < n2 / 4; i += stride) ((float4*)g_agg2)[i] = z;
    for (size_t i = i0; i < N_NODES; i += stride) g_cnt[i] = 0.0f;
}

// ---- build fused transposed weight for layer 1 ----
__global__ void k_W1t(const float* __restrict__ W1l, const float* __restrict__ W1r) {
    int idx = blockIdx.x * blockDim.x + threadIdx.x;   // 0 .. 256*256-1
    if (idx >= KTOT * HIDDEN) return;
    int k = idx >> 8;          // 0..255
    int h = idx & 255;
    g_W1t[idx] = (k < IN_FEAT) ? W1l[h * IN_FEAT + k]
                               : W1r[h * IN_FEAT + (k - IN_FEAT)];
}

// ---- scatter layer 1: agg1[dst] += x[src]; cnt[dst] += 1  (warp per edge) ----
__global__ void k_scatter1(const float* __restrict__ x,
                           const int* __restrict__ src,
                           const int* __restrict__ dst, int E) {
    int gw   = (blockIdx.x * blockDim.x + threadIdx.x) >> 5;
    int lane = threadIdx.x & 31;
    if (gw >= E) return;
    int s = src[gw];
    int d = dst[gw];
    float4 v = ((const float4*)(x + (size_t)s * IN_FEAT))[lane];  // 32 lanes * 4 = 128
    float* o = g_agg1 + (size_t)d * IN_FEAT + lane * 4;
    atomicAdd(o + 0, v.x);
    atomicAdd(o + 1, v.y);
    atomicAdd(o + 2, v.z);
    atomicAdd(o + 3, v.w);
    if (lane == 0) atomicAdd(&g_cnt[d], 1.0f);
}

// ---- inv count ----
__global__ void k_inv() {
    int n = blockIdx.x * blockDim.x + threadIdx.x;
    if (n < N_NODES) g_inv[n] = 1.0f / fmaxf(g_cnt[n], 1.0f);
}

// ---- layer 1: h1 = relu(l2norm( [agg|x] @ W1t + b1 ))  (64x256 tile SGEMM) ----
__global__ void __launch_bounds__(256) k_layer1(const float* __restrict__ x,
                                                const float* __restrict__ b1) {
    __shared__ float As[32][68];      // [k][row], padded
    __shared__ float Bs[32][HIDDEN];  // [k][h]
    __shared__ float sInv[64];

    const int t  = threadIdx.x;
    const int tx = t & 31;            // col group: cols tx*8 .. tx*8+7
    const int ty = t >> 5;            // warp id = row group: rows ty*8 .. ty*8+7
    const int n0 = blockIdx.x * 64;

    if (t < 64) {
        int n = n0 + t;
        sInv[t] = (n < N_NODES) ? g_inv[n] : 0.0f;
    }
    float acc[8][8];
#pragma unroll
    for (int i = 0; i < 8; i++)
#pragma unroll
        for (int j = 0; j < 8; j++) acc[i][j] = 0.0f;
    __syncthreads();

    for (int k0 = 0; k0 < KTOT; k0 += 32) {
        // load A tile: 64 rows x 32 k  (512 float4, 2 per thread), store transposed
#pragma unroll
        for (int j = 0; j < 2; j++) {
            int idx = t * 2 + j;
            int row = idx >> 3;
            int kq  = idx & 7;
            int n   = n0 + row;
            float4 v = make_float4(0.f, 0.f, 0.f, 0.f);
            if (n < N_NODES) {
                int kk = k0 + kq * 4;
                if (kk < IN_FEAT) {
                    v = *(const float4*)(g_agg1 + (size_t)n * IN_FEAT + kk);
                    float sc = sInv[row];
                    v.x *= sc; v.y *= sc; v.z *= sc; v.w *= sc;
                } else {
                    v = *(const float4*)(x + (size_t)n * IN_FEAT + (kk - IN_FEAT));
                }
            }
            As[kq * 4 + 0][row] = v.x;
            As[kq * 4 + 1][row] = v.y;
            As[kq * 4 + 2][row] = v.z;
            As[kq * 4 + 3][row] = v.w;
        }
        // load B tile: 32 k x 256 h (2048 float4, 8 per thread), coalesced
#pragma unroll
        for (int j = 0; j < 8; j++) {
            int fidx = t + j * 256;       // 0..2047
            int k    = fidx >> 6;
            int hq   = fidx & 63;
            float4 v = *(const float4*)(g_W1t + (size_t)(k0 + k) * HIDDEN + hq * 4);
            *(float4*)&Bs[k][hq * 4] = v;
        }
        __syncthreads();

#pragma unroll
        for (int k = 0; k < 32; k++) {
            float a[8], b[8];
#pragma unroll
            for (int i = 0; i < 8; i++) a[i] = As[k][ty * 8 + i];
            float4 bv0 = *(const float4*)&Bs[k][tx * 8];
            float4 bv1 = *(const float4*)&Bs[k][tx * 8 + 4];
            b[0] = bv0.x; b[1] = bv0.y; b[2] = bv0.z; b[3] = bv0.w;
            b[4] = bv1.x; b[5] = bv1.y; b[6] = bv1.z; b[7] = bv1.w;
#pragma unroll
            for (int i = 0; i < 8; i++)
#pragma unroll
                for (int j = 0; j < 8; j++) acc[i][j] += a[i] * b[j];
        }
        __syncthreads();
    }

    // epilogue: +bias, L2 normalize per row (warp owns full row), relu, store
    float bias[8];
    {
        float4 t0 = *(const float4*)(b1 + tx * 8);
        float4 t1 = *(const float4*)(b1 + tx * 8 + 4);
        bias[0] = t0.x; bias[1] = t0.y; bias[2] = t0.z; bias[3] = t0.w;
        bias[4] = t1.x; bias[5] = t1.y; bias[6] = t1.z; bias[7] = t1.w;
    }
#pragma unroll
    for (int i = 0; i < 8; i++) {
        int n = n0 + ty * 8 + i;
        float v[8];
        float ss = 0.0f;
#pragma unroll
        for (int j = 0; j < 8; j++) {
            v[j] = acc[i][j] + bias[j];
            ss += v[j] * v[j];
        }
#pragma unroll
        for (int o = 16; o > 0; o >>= 1) ss += __shfl_xor_sync(0xffffffffu, ss, o);
        float sc = 1.0f / fmaxf(sqrtf(ss), 1e-12f);
        if (n < N_NODES) {
            float4 o0 = make_float4(fmaxf(v[0] * sc, 0.f), fmaxf(v[1] * sc, 0.f),
                                    fmaxf(v[2] * sc, 0.f), fmaxf(v[3] * sc, 0.f));
            float4 o1 = make_float4(fmaxf(v[4] * sc, 0.f), fmaxf(v[5] * sc, 0.f),
                                    fmaxf(v[6] * sc, 0.f), fmaxf(v[7] * sc, 0.f));
            *(float4*)(g_h1 + (size_t)n * HIDDEN + tx * 8)     = o0;
            *(float4*)(g_h1 + (size_t)n * HIDDEN + tx * 8 + 4) = o1;
        }
    }
}

// ---- scatter layer 2: agg2[dst] += h1[src]  (warp per edge, 256 floats) ----
__global__ void k_scatter2(const int* __restrict__ src,
                           const int* __restrict__ dst, int E) {
    int gw   = (blockIdx.x * blockDim.x + threadIdx.x) >> 5;
    int lane = threadIdx.x & 31;
    if (gw >= E) return;
    int s = src[gw];
    int d = dst[gw];
    const float4* hv = (const float4*)(g_h1 + (size_t)s * HIDDEN);
    float4 v0 = hv[lane];
    float4 v1 = hv[lane + 32];
    float* o = g_agg2 + (size_t)d * HIDDEN;
    atomicAdd(o + lane * 4 + 0,   v0.x);
    atomicAdd(o + lane * 4 + 1,   v0.y);
    atomicAdd(o + lane * 4 + 2,   v0.z);
    atomicAdd(o + lane * 4 + 3,   v0.w);
    atomicAdd(o + 128 + lane * 4 + 0, v1.x);
    atomicAdd(o + 128 + lane * 4 + 1, v1.y);
    atomicAdd(o + 128 + lane * 4 + 2, v1.z);
    atomicAdd(o + 128 + lane * 4 + 3, v1.w);
}

// ---- layer 2 + l2norm + log_softmax (warp per node) ----
__global__ void __launch_bounds__(256) k_layer2(const float* __restrict__ W2l,
                                                const float* __restrict__ b2,
                                                const float* __restrict__ W2r,
                                                float* __restrict__ out) {
    __shared__ float sW[4][HIDDEN];  // rows: W2l[0], W2l[1], W2r[0], W2r[1]
    int t = threadIdx.x;
    for (int i = t; i < 4 * HIDDEN; i += 256) {
        int m = i >> 8;
        int k = i & 255;
        sW[m][k] = (m < 2) ? W2l[m * HIDDEN + k] : W2r[(m - 2) * HIDDEN + k];
    }
    __syncthreads();

    int node = blockIdx.x * 8 + (t >> 5);
    int lane = t & 31;
    if (node >= N_NODES) return;

    float inv = g_inv[node];
    const float* ar = g_agg2 + (size_t)node * HIDDEN;
    const float* hr = g_h1   + (size_t)node * HIDDEN;
    float a0 = 0.f, a1 = 0.f;
#pragma unroll
    for (int q = 0; q < 8; q++) {
        int k  = lane + q * 32;
        float a = ar[k] * inv;
        float h = hr[k];
        a0 += a * sW[0][k] + h * sW[2][k];
        a1 += a * sW[1][k] + h * sW[3][k];
    }
#pragma unroll
    for (int o = 16; o > 0; o >>= 1) {
        a0 += __shfl_xor_sync(0xffffffffu, a0, o);
        a1 += __shfl_xor_sync(0xffffffffu, a1, o);
    }
    if (lane == 0) {
        float v0 = a0 + b2[0];
        float v1 = a1 + b2[1];
        float s = 1.0f / fmaxf(sqrtf(v0 * v0 + v1 * v1), 1e-12f);
        v0 *= s; v1 *= s;
        float m = fmaxf(v0, v1);
        float l = m + logf(expf(v0 - m) + expf(v1 - m));
        out[(size_t)node * 2 + 0] = v0 - l;
        out[(size_t)node * 2 + 1] = v1 - l;
    }
}

extern "C" void kernel_launch(void* const* d_in, const int* in_sizes, int n_in,
                              void* d_out, int out_size) {
    const float* x   = (const float*)d_in[0];
    const int*   ei  = (const int*)d_in[1];     // harness canonicalizes ints to int32
    const float* W1l = (const float*)d_in[2];
    const float* b1  = (const float*)d_in[3];
    const float* W1r = (const float*)d_in[4];
    const float* W2l = (const float*)d_in[5];
    const float* b2  = (const float*)d_in[6];
    const float* W2r = (const float*)d_in[7];
    float*       out = (float*)d_out;

    int E = in_sizes[1] / 2;
    const int* src = ei;
    const int* dst = ei + E;

    k_zero<<<592, 256>>>();   // 148 SMs * 4 blocks
    k_W1t<<<(KTOT * HIDDEN + 255) / 256, 256>>>(W1l, W1r);
    k_scatter1<<<(E * 32 + 255) / 256, 256>>>(x, src, dst, E);
    k_inv<<<(N_NODES + 255) / 256, 256>>>();
    k_layer1<<<(N_NODES + 63) / 64, 256>>>(x, b1);
    k_scatter2<<<(E * 32 + 255) / 256, 256>>>(src, dst, E);
    k_layer2<<<(N_NODES + 7) / 8, 256>>>(W2l, b2, W2r, out);
}

// round 4
// speedup vs baseline: 2.3294x; 2.3294x over previous
#include <cuda_runtime.h>
#include <math.h>

#define N_NODES 100000
#define IN_FEAT 128
#define HIDDEN 256
#define KTOT (2*IN_FEAT)   // concat [agg | x] -> K=256 for layer-1 GEMM

// ---- scratch (static device globals; no allocation allowed) ----
__device__ float  g_agg1[(size_t)N_NODES * IN_FEAT];   // 51.2 MB
__device__ float  g_cnt [N_NODES];
__device__ float  g_inv [N_NODES];
__device__ float2 g_zl  [N_NODES];                     // h1 @ W2_l^T  (per node, 2 floats)
__device__ float2 g_zr  [N_NODES];                     // h1 @ W2_r^T
__device__ float2 g_agg2s[N_NODES];                    // scattered zl sums
__device__ float  g_W1t [KTOT * HIDDEN];               // fused [W1_l | W1_r] transposed

// ---- zero scratch (graph-capturable) ----
__global__ void k_zero() {
    const size_t n1 = (size_t)N_NODES * IN_FEAT;   // g_agg1
    size_t stride = (size_t)gridDim.x * blockDim.x;
    size_t i0 = (size_t)blockIdx.x * blockDim.x + threadIdx.x;
    float4 z4 = make_float4(0.f, 0.f, 0.f, 0.f);
    for (size_t i = i0; i < n1 / 4; i += stride) ((float4*)g_agg1)[i] = z4;
    for (size_t i = i0; i < N_NODES; i += stride) {
        g_cnt[i] = 0.0f;
        g_agg2s[i] = make_float2(0.f, 0.f);
    }
}

// ---- build fused transposed weight for layer 1 ----
__global__ void k_W1t(const float* __restrict__ W1l, const float* __restrict__ W1r) {
    int idx = blockIdx.x * blockDim.x + threadIdx.x;   // 0 .. 256*256-1
    if (idx >= KTOT * HIDDEN) return;
    int k = idx >> 8;          // 0..255
    int h = idx & 255;
    g_W1t[idx] = (k < IN_FEAT) ? W1l[h * IN_FEAT + k]
                               : W1r[h * IN_FEAT + (k - IN_FEAT)];
}

// ---- scatter layer 1: agg1[dst] += x[src]; cnt[dst] += 1  (warp per edge) ----
__global__ void k_scatter1(const float* __restrict__ x,
                           const int* __restrict__ src,
                           const int* __restrict__ dst, int E) {
    int gw   = (blockIdx.x * blockDim.x + threadIdx.x) >> 5;
    int lane = threadIdx.x & 31;
    if (gw >= E) return;
    int s = src[gw];
    int d = dst[gw];
    float4 v = ((const float4*)(x + (size_t)s * IN_FEAT))[lane];  // 32 lanes * 4 = 128
    float* o = g_agg1 + (size_t)d * IN_FEAT + lane * 4;
    asm volatile("red.global.add.v4.f32 [%0], {%1, %2, %3, %4};"
                 :: "l"(o), "f"(v.x), "f"(v.y), "f"(v.z), "f"(v.w) : "memory");
    if (lane == 0)
        asm volatile("red.global.add.f32 [%0], %1;"
                     :: "l"(&g_cnt[d]), "f"(1.0f) : "memory");
}

// ---- inv count ----
__global__ void k_inv() {
    int n = blockIdx.x * blockDim.x + threadIdx.x;
    if (n < N_NODES) g_inv[n] = 1.0f / fmaxf(g_cnt[n], 1.0f);
}

// ---- layer 1 + fused layer-2 projections ----
// h1 = relu(l2norm([agg|x] @ W1t + b1));  zl = h1@W2l^T, zr = h1@W2r^T (h1 never stored)
__global__ void __launch_bounds__(256) k_layer1(const float* __restrict__ x,
                                                const float* __restrict__ b1,
                                                const float* __restrict__ W2l,
                                                const float* __restrict__ W2r) {
    __shared__ float As[32][72];      // [k][row], padded (72 -> 16B-aligned rows)
    __shared__ float Bs[32][HIDDEN];  // [k][h]
    __shared__ float sInv[64];
    __shared__ float sW2[4][HIDDEN];  // W2l[0], W2l[1], W2r[0], W2r[1]

    const int t  = threadIdx.x;
    const int tx = t & 31;            // col group: cols tx*8 .. tx*8+7
    const int ty = t >> 5;            // warp id = row group: rows ty*8 .. ty*8+7
    const int n0 = blockIdx.x * 64;

    if (t < 64) {
        int n = n0 + t;
        sInv[t] = (n < N_NODES) ? g_inv[n] : 0.0f;
    }
    for (int i = t; i < 4 * HIDDEN; i += 256) {
        int m = i >> 8, k = i & 255;
        sW2[m][k] = (m < 2) ? W2l[m * HIDDEN + k] : W2r[(m - 2) * HIDDEN + k];
    }

    float acc[8][8];
#pragma unroll
    for (int i = 0; i < 8; i++)
#pragma unroll
        for (int j = 0; j < 8; j++) acc[i][j] = 0.0f;
    __syncthreads();

    for (int k0 = 0; k0 < KTOT; k0 += 32) {
        // load A tile: 64 rows x 32 k (512 float4, 2 per thread), store transposed
#pragma unroll
        for (int j = 0; j < 2; j++) {
            int idx = t * 2 + j;
            int row = idx >> 3;
            int kq  = idx & 7;
            int n   = n0 + row;
            float4 v = make_float4(0.f, 0.f, 0.f, 0.f);
            if (n < N_NODES) {
                int kk = k0 + kq * 4;
                if (kk < IN_FEAT) {
                    v = *(const float4*)(g_agg1 + (size_t)n * IN_FEAT + kk);
                    float sc = sInv[row];
                    v.x *= sc; v.y *= sc; v.z *= sc; v.w *= sc;
                } else {
                    v = *(const float4*)(x + (size_t)n * IN_FEAT + (kk - IN_FEAT));
                }
            }
            As[kq * 4 + 0][row] = v.x;
            As[kq * 4 + 1][row] = v.y;
            As[kq * 4 + 2][row] = v.z;
            As[kq * 4 + 3][row] = v.w;
        }
        // load B tile: 32 k x 256 h (2048 float4, 8 per thread), coalesced
#pragma unroll
        for (int j = 0; j < 8; j++) {
            int fidx = t + j * 256;       // 0..2047
            int k    = fidx >> 6;
            int hq   = fidx & 63;
            float4 v = *(const float4*)(g_W1t + (size_t)(k0 + k) * HIDDEN + hq * 4);
            *(float4*)&Bs[k][hq * 4] = v;
        }
        __syncthreads();

#pragma unroll
        for (int k = 0; k < 32; k++) {
            float a[8], b[8];
#pragma unroll
            for (int i = 0; i < 8; i++) a[i] = As[k][ty * 8 + i];
            float4 bv0 = *(const float4*)&Bs[k][tx * 8];
            float4 bv1 = *(const float4*)&Bs[k][tx * 8 + 4];
            b[0] = bv0.x; b[1] = bv0.y; b[2] = bv0.z; b[3] = bv0.w;
            b[4] = bv1.x; b[5] = bv1.y; b[6] = bv1.z; b[7] = bv1.w;
#pragma unroll
            for (int i = 0; i < 8; i++)
#pragma unroll
                for (int j = 0; j < 8; j++) acc[i][j] += a[i] * b[j];
        }
        __syncthreads();
    }

    // epilogue: +bias, L2 normalize per row (warp owns full row), relu,
    // then project onto W2 rows (4 dots) and warp-reduce; store zl/zr only.
    float bias[8];
    {
        float4 t0 = *(const float4*)(b1 + tx * 8);
        float4 t1 = *(const float4*)(b1 + tx * 8 + 4);
        bias[0] = t0.x; bias[1] = t0.y; bias[2] = t0.z; bias[3] = t0.w;
        bias[4] = t1.x; bias[5] = t1.y; bias[6] = t1.z; bias[7] = t1.w;
    }
#pragma unroll
    for (int i = 0; i < 8; i++) {
        int n = n0 + ty * 8 + i;
        float v[8];
        float ss = 0.0f;
#pragma unroll
        for (int j = 0; j < 8; j++) {
            v[j] = acc[i][j] + bias[j];
            ss += v[j] * v[j];
        }
#pragma unroll
        for (int o = 16; o > 0; o >>= 1) ss += __shfl_xor_sync(0xffffffffu, ss, o);
        float sc = 1.0f / fmaxf(sqrtf(ss), 1e-12f);

        float d0 = 0.f, d1 = 0.f, d2 = 0.f, d3 = 0.f;
#pragma unroll
        for (int j = 0; j < 8; j++) {
            float h = fmaxf(v[j] * sc, 0.0f);     // relu(l2norm) = h1 value
            int c = tx * 8 + j;
            d0 += h * sW2[0][c];
            d1 += h * sW2[1][c];
            d2 += h * sW2[2][c];
            d3 += h * sW2[3][c];
        }
#pragma unroll
        for (int o = 16; o > 0; o >>= 1) {
            d0 += __shfl_xor_sync(0xffffffffu, d0, o);
            d1 += __shfl_xor_sync(0xffffffffu, d1, o);
            d2 += __shfl_xor_sync(0xffffffffu, d2, o);
            d3 += __shfl_xor_sync(0xffffffffu, d3, o);
        }
        if (tx == 0 && n < N_NODES) {
            g_zl[n] = make_float2(d0, d1);
            g_zr[n] = make_float2(d2, d3);
        }
    }
}

// ---- scatter layer 2 (tiny): agg2s[dst] += zl[src]  (thread per edge) ----
__global__ void k_scatter2(const int* __restrict__ src,
                           const int* __restrict__ dst, int E) {
    int e = blockIdx.x * blockDim.x + threadIdx.x;
    if (e >= E) return;
    int s = src[e];
    int d = dst[e];
    float2 z = g_zl[s];
    asm volatile("red.global.add.v2.f32 [%0], {%1, %2};"
                 :: "l"(&g_agg2s[d]), "f"(z.x), "f"(z.y) : "memory");
}

// ---- final: l2norm(agg2s*inv + zr + b2) -> log_softmax (thread per node) ----
__global__ void k_final(const float* __restrict__ b2, float* __restrict__ out) {
    int n = blockIdx.x * blockDim.x + threadIdx.x;
    if (n >= N_NODES) return;
    float inv = g_inv[n];
    float2 a = g_agg2s[n];
    float2 r = g_zr[n];
    float v0 = a.x * inv + r.x + b2[0];
    float v1 = a.y * inv + r.y + b2[1];
    float s = 1.0f / fmaxf(sqrtf(v0 * v0 + v1 * v1), 1e-12f);
    v0 *= s; v1 *= s;
    float m = fmaxf(v0, v1);
    float l = m + logf(expf(v0 - m) + expf(v1 - m));
    out[(size_t)n * 2 + 0] = v0 - l;
    out[(size_t)n * 2 + 1] = v1 - l;
}

extern "C" void kernel_launch(void* const* d_in, const int* in_sizes, int n_in,
                              void* d_out, int out_size) {
    const float* x   = (const float*)d_in[0];
    const int*   ei  = (const int*)d_in[1];     // harness canonicalizes ints to int32
    const float* W1l = (const float*)d_in[2];
    const float* b1  = (const float*)d_in[3];
    const float* W1r = (const float*)d_in[4];
    const float* W2l = (const float*)d_in[5];
    const float* b2  = (const float*)d_in[6];
    const float* W2r = (const float*)d_in[7];
    float*       out = (float*)d_out;

    int E = in_sizes[1] / 2;
    const int* src = ei;
    const int* dst = ei + E;

    k_zero<<<592, 256>>>();
    k_W1t<<<(KTOT * HIDDEN + 255) / 256, 256>>>(W1l, W1r);
    k_scatter1<<<(E * 32 + 255) / 256, 256>>>(x, src, dst, E);
    k_inv<<<(N_NODES + 255) / 256, 256>>>();
    k_layer1<<<(N_NODES + 63) / 64, 256>>>(x, b1, W2l, W2r);
    k_scatter2<<<(E + 255) / 256, 256>>>(src, dst, E);
    k_final<<<(N_NODES + 255) / 256, 256>>>(b2, out);
}

// round 6
// speedup vs baseline: 3.1108x; 1.3355x over previous
#include <cuda_runtime.h>
#include <cuda_bf16.h>
#include <math.h>
#include <stdint.h>

#define N_NODES 100000
#define N_PAD   100096            // 782 * 128
#define IN_FEAT 128
#define HIDDEN  256
#define N_TILES 782

// ---------------- scratch (static device globals) ----------------
__device__ float  g_agg1[(size_t)N_NODES * IN_FEAT];    // 51.2 MB
__device__ float  g_cnt [N_NODES];
__device__ float  g_inv [N_NODES];
__device__ float2 g_zl  [N_NODES];
__device__ float2 g_zr  [N_NODES];
__device__ float2 g_agg2s[N_NODES];
__device__ __nv_bfloat16 g_Ahi[(size_t)N_PAD * 256];    // [n][0:128]=agg*inv, [128:256]=x (hi)
__device__ __nv_bfloat16 g_Alo[(size_t)N_PAD * 256];    // lo split (padding rows stay 0)
__device__ __nv_bfloat16 g_Whi[256 * 256];              // B[n=256][k=256] (hi)
__device__ __nv_bfloat16 g_Wlo[256 * 256];              // lo

// ---------------- helpers ----------------
__device__ __forceinline__ uint32_t smem_u32(const void* p) {
    uint32_t a;
    asm("{ .reg .u64 t; cvta.to.shared.u64 t, %1; cvt.u32.u64 %0, t; }" : "=r"(a) : "l"(p));
    return a;
}
__device__ __forceinline__ void ldsm_x4(uint32_t* r, uint32_t addr) {
    asm volatile("ldmatrix.sync.aligned.m8n8.x4.shared.b16 {%0,%1,%2,%3}, [%4];"
                 : "=r"(r[0]), "=r"(r[1]), "=r"(r[2]), "=r"(r[3]) : "r"(addr));
}
__device__ __forceinline__ void mma_bf16(float* d, const uint32_t* a, uint32_t b0, uint32_t b1) {
    asm volatile("mma.sync.aligned.m16n8k16.row.col.f32.bf16.bf16.f32 "
                 "{%0,%1,%2,%3}, {%4,%5,%6,%7}, {%8,%9}, {%0,%1,%2,%3};"
                 : "+f"(d[0]), "+f"(d[1]), "+f"(d[2]), "+f"(d[3])
                 : "r"(a[0]), "r"(a[1]), "r"(a[2]), "r"(a[3]), "r"(b0), "r"(b1));
}

// SMEM layout (dynamic), 80B-padded rows (5 mod 8 chunks -> conflict-free ldmatrix)
#define OFF_AH   0u        // 128*80
#define OFF_AL   10240u    // 128*80
#define OFF_BH   20480u    // 256*80
#define OFF_BL   40960u    // 256*80
#define OFF_W2   61440u    // 4*256 f32
#define OFF_B1   65536u    // 256 f32
#define OFF_NORM 66560u    // 128 f32
#define OFF_Z    67072u    // 128*4 f32
#define SMEM_DYN 69120

// ---------------- small kernels ----------------
__global__ void k_zero() {
    const size_t n1 = (size_t)N_NODES * IN_FEAT;
    size_t stride = (size_t)gridDim.x * blockDim.x;
    size_t i0 = (size_t)blockIdx.x * blockDim.x + threadIdx.x;
    float4 z4 = make_float4(0.f, 0.f, 0.f, 0.f);
    for (size_t i = i0; i < n1 / 4; i += stride) ((float4*)g_agg1)[i] = z4;
    for (size_t i = i0; i < N_NODES; i += stride) {
        g_cnt[i] = 0.0f;
        g_agg2s[i] = make_float2(0.f, 0.f);
    }
}

__global__ void k_Wsplit(const float* __restrict__ W1l, const float* __restrict__ W1r) {
    int idx = blockIdx.x * blockDim.x + threadIdx.x;   // 0..65535
    if (idx >= 256 * 256) return;
    int h = idx >> 8, k = idx & 255;
    float v = (k < 128) ? W1l[h * 128 + k] : W1r[h * 128 + (k - 128)];
    __nv_bfloat16 hi = __float2bfloat16(v);
    __nv_bfloat16 lo = __float2bfloat16(v - __bfloat162float(hi));
    g_Whi[idx] = hi;
    g_Wlo[idx] = lo;
}

__global__ void k_scatter1(const float* __restrict__ x,
                           const int* __restrict__ src,
                           const int* __restrict__ dst, int E) {
    int gw   = (blockIdx.x * blockDim.x + threadIdx.x) >> 5;
    int lane = threadIdx.x & 31;
    if (gw >= E) return;
    int s = src[gw];
    int d = dst[gw];
    float4 v = ((const float4*)(x + (size_t)s * IN_FEAT))[lane];
    float* o = g_agg1 + (size_t)d * IN_FEAT + lane * 4;
    asm volatile("red.global.add.v4.f32 [%0], {%1, %2, %3, %4};"
                 :: "l"(o), "f"(v.x), "f"(v.y), "f"(v.z), "f"(v.w) : "memory");
    if (lane == 0)
        asm volatile("red.global.add.f32 [%0], %1;"
                     :: "l"(&g_cnt[d]), "f"(1.0f) : "memory");
}

__global__ void k_inv() {
    int n = blockIdx.x * blockDim.x + threadIdx.x;
    if (n < N_NODES) g_inv[n] = 1.0f / fmaxf(g_cnt[n], 1.0f);
}

// A = [agg*inv | x] -> bf16 hi/lo splits. One thread per 4 elements.
__global__ void k_conv(const float* __restrict__ x) {
    size_t i = (size_t)blockIdx.x * blockDim.x + threadIdx.x;
    const size_t TOT = (size_t)N_NODES * 64;
    if (i >= TOT) return;
    int n = (int)(i >> 6);
    int c = (int)(i & 63) * 4;
    float4 v;
    if (c < 128) {
        v = *(const float4*)(g_agg1 + (size_t)n * 128 + c);
        float iv = g_inv[n];
        v.x *= iv; v.y *= iv; v.z *= iv; v.w *= iv;
    } else {
        v = *(const float4*)(x + (size_t)n * 128 + (c - 128));
    }
    __nv_bfloat16 h0 = __float2bfloat16(v.x), h1 = __float2bfloat16(v.y);
    __nv_bfloat16 h2 = __float2bfloat16(v.z), h3 = __float2bfloat16(v.w);
    __nv_bfloat16 l0 = __float2bfloat16(v.x - __bfloat162float(h0));
    __nv_bfloat16 l1 = __float2bfloat16(v.y - __bfloat162float(h1));
    __nv_bfloat16 l2 = __float2bfloat16(v.z - __bfloat162float(h2));
    __nv_bfloat16 l3 = __float2bfloat16(v.w - __bfloat162float(h3));
    __nv_bfloat162* ph = (__nv_bfloat162*)(g_Ahi + (size_t)n * 256 + c);
    __nv_bfloat162* pl = (__nv_bfloat162*)(g_Alo + (size_t)n * 256 + c);
    ph[0] = __halves2bfloat162(h0, h1);
    ph[1] = __halves2bfloat162(h2, h3);
    pl[0] = __halves2bfloat162(l0, l1);
    pl[1] = __halves2bfloat162(l2, l3);
}

// ---------------- HMMA GEMM: block tile M=128, N=256(full), K=256 ----------------
// acc = Ahi@Whi^T + Ahi@Wlo^T + Alo@Whi^T; epilogue: +b1, l2norm, relu, W2 proj -> zl/zr
__global__ void __launch_bounds__(512, 1) k_gemm(const float* __restrict__ b1,
                                                 const float* __restrict__ W2l,
                                                 const float* __restrict__ W2r) {
    extern __shared__ char smem[];
    const int t    = threadIdx.x;
    const int lane = t & 31;
    const int wid  = t >> 5;
    const int wm   = wid >> 2;        // 0..3 (m strip of 32)
    const int wn   = wid & 3;         // 0..3 (n strip of 64)
    const int n0   = blockIdx.x * 128;

    float* sW2   = (float*)(smem + OFF_W2);
    float* sB1   = (float*)(smem + OFF_B1);
    float* sNorm = (float*)(smem + OFF_NORM);
    float* sZ    = (float*)(smem + OFF_Z);

    for (int i = t; i < 256; i += 512) sB1[i] = b1[i];
    for (int i = t; i < 1024; i += 512) {
        int m = i >> 8, k = i & 255;
        sW2[i] = (m < 2) ? W2l[m * 256 + k] : W2r[(m - 2) * 256 + k];
    }
    if (t < 128) {
        sNorm[t] = 0.f;
        ((float4*)sZ)[t] = make_float4(0.f, 0.f, 0.f, 0.f);
    }

    const uint32_t smb  = smem_u32(smem);
    const uint32_t rowo = (lane & 7) + ((lane >> 3) & 1) * 8;  // ldmatrix row offset
    const uint32_t kB   = (lane >> 4) * 16;                    // ldmatrix k-byte offset

    float acc[2][8][4];
#pragma unroll
    for (int a = 0; a < 2; a++)
#pragma unroll
        for (int b = 0; b < 8; b++)
#pragma unroll
            for (int c = 0; c < 4; c++) acc[a][b][c] = 0.f;

    // load indices (16B per thread per buffer-pass)
    const int lrow = t >> 2;      // 0..127
    const int lc4  = t & 3;       // 0..3

    for (int kc = 0; kc < 256; kc += 32) {
        // A tiles: 128 rows x 32 bf16
        {
            const uint4* ga = (const uint4*)(g_Ahi + (size_t)(n0 + lrow) * 256 + kc + lc4 * 8);
            *(uint4*)(smem + OFF_AH + lrow * 80 + lc4 * 16) = *ga;
            const uint4* gl = (const uint4*)(g_Alo + (size_t)(n0 + lrow) * 256 + kc + lc4 * 8);
            *(uint4*)(smem + OFF_AL + lrow * 80 + lc4 * 16) = *gl;
        }
        // B tiles: 256 rows x 32 bf16
#pragma unroll
        for (int i = 0; i < 2; i++) {
            int idx = t + i * 512;
            int br = idx >> 2, bc = idx & 3;
            *(uint4*)(smem + OFF_BH + br * 80 + bc * 16) =
                *(const uint4*)(g_Whi + (size_t)br * 256 + kc + bc * 8);
            *(uint4*)(smem + OFF_BL + br * 80 + bc * 16) =
                *(const uint4*)(g_Wlo + (size_t)br * 256 + kc + bc * 8);
        }
        __syncthreads();

#pragma unroll
        for (int s = 0; s < 2; s++) {
            uint32_t ah[2][4], al[2][4];
#pragma unroll
            for (int tm = 0; tm < 2; tm++) {
                uint32_t r = (wm * 32 + tm * 16 + rowo) * 80 + s * 32 + kB;
                ldsm_x4(ah[tm], smb + OFF_AH + r);
                ldsm_x4(al[tm], smb + OFF_AL + r);
            }
#pragma unroll
            for (int tp = 0; tp < 4; tp++) {
                uint32_t br = (wn * 64 + tp * 16 + rowo) * 80 + s * 32 + kB;
                uint32_t bh[4], bl[4];
                ldsm_x4(bh, smb + OFF_BH + br);
                ldsm_x4(bl, smb + OFF_BL + br);
#pragma unroll
                for (int tm = 0; tm < 2; tm++) {
                    mma_bf16(acc[tm][2 * tp],     ah[tm], bh[0], bh[2]);
                    mma_bf16(acc[tm][2 * tp],     al[tm], bh[0], bh[2]);
                    mma_bf16(acc[tm][2 * tp],     ah[tm], bl[0], bl[2]);
                    mma_bf16(acc[tm][2 * tp + 1], ah[tm], bh[1], bh[3]);
                    mma_bf16(acc[tm][2 * tp + 1], al[tm], bh[1], bh[3]);
                    mma_bf16(acc[tm][2 * tp + 1], ah[tm], bl[1], bl[3]);
                }
            }
        }
        __syncthreads();
    }

    // ---- epilogue ----
    // phase A: +bias, per-row sum of squares
#pragma unroll
    for (int tm = 0; tm < 2; tm++) {
        float s0 = 0.f, s1 = 0.f;
#pragma unroll
        for (int tn = 0; tn < 8; tn++) {
            int c0 = wn * 64 + tn * 8 + (lane & 3) * 2;
            float b0v = sB1[c0], b1v = sB1[c0 + 1];
            acc[tm][tn][0] += b0v;
            acc[tm][tn][1] += b1v;
            acc[tm][tn][2] += b0v;
            acc[tm][tn][3] += b1v;
            s0 += acc[tm][tn][0] * acc[tm][tn][0] + acc[tm][tn][1] * acc[tm][tn][1];
            s1 += acc[tm][tn][2] * acc[tm][tn][2] + acc[tm][tn][3] * acc[tm][tn][3];
        }
        s0 += __shfl_xor_sync(0xffffffffu, s0, 1);
        s0 += __shfl_xor_sync(0xffffffffu, s0, 2);
        s1 += __shfl_xor_sync(0xffffffffu, s1, 1);
        s1 += __shfl_xor_sync(0xffffffffu, s1, 2);
        if ((lane & 3) == 0) {
            int r = wm * 32 + tm * 16 + (lane >> 2);
            atomicAdd(&sNorm[r], s0);
            atomicAdd(&sNorm[r + 8], s1);
        }
    }
    __syncthreads();
    if (t < 128) sNorm[t] = 1.0f / fmaxf(sqrtf(sNorm[t]), 1e-12f);
    __syncthreads();

    // phase C: relu(norm), project onto W2 rows
#pragma unroll
    for (int tm = 0; tm < 2; tm++) {
        int rbase = wm * 32 + tm * 16 + (lane >> 2);
        float rc0 = sNorm[rbase], rc1 = sNorm[rbase + 8];
        float d0[4] = {0.f, 0.f, 0.f, 0.f};
        float d1[4] = {0.f, 0.f, 0.f, 0.f};
#pragma unroll
        for (int tn = 0; tn < 8; tn++) {
            int c0 = wn * 64 + tn * 8 + (lane & 3) * 2;
            float h00 = fmaxf(acc[tm][tn][0] * rc0, 0.f);
            float h01 = fmaxf(acc[tm][tn][1] * rc0, 0.f);
            float h10 = fmaxf(acc[tm][tn][2] * rc1, 0.f);
            float h11 = fmaxf(acc[tm][tn][3] * rc1, 0.f);
#pragma unroll
            for (int o = 0; o < 4; o++) {
                float w0 = sW2[o * 256 + c0], w1 = sW2[o * 256 + c0 + 1];
                d0[o] += h00 * w0 + h01 * w1;
                d1[o] += h10 * w0 + h11 * w1;
            }
        }
#pragma unroll
        for (int o = 0; o < 4; o++) {
            d0[o] += __shfl_xor_sync(0xffffffffu, d0[o], 1);
            d0[o] += __shfl_xor_sync(0xffffffffu, d0[o], 2);
            d1[o] += __shfl_xor_sync(0xffffffffu, d1[o], 1);
            d1[o] += __shfl_xor_sync(0xffffffffu, d1[o], 2);
        }
        if ((lane & 3) == 0) {
#pragma unroll
            for (int o = 0; o < 4; o++) {
                atomicAdd(&sZ[rbase * 4 + o], d0[o]);
                atomicAdd(&sZ[(rbase + 8) * 4 + o], d1[o]);
            }
        }
    }
    __syncthreads();
    if (t < 128) {
        int n = n0 + t;
        if (n < N_NODES) {
            g_zl[n] = make_float2(sZ[t * 4 + 0], sZ[t * 4 + 1]);
            g_zr[n] = make_float2(sZ[t * 4 + 2], sZ[t * 4 + 3]);
        }
    }
}

// ---------------- scatter layer 2 + final ----------------
__global__ void k_scatter2(const int* __restrict__ src,
                           const int* __restrict__ dst, int E) {
    int e = blockIdx.x * blockDim.x + threadIdx.x;
    if (e >= E) return;
    int s = src[e];
    int d = dst[e];
    float2 z = g_zl[s];
    asm volatile("red.global.add.v2.f32 [%0], {%1, %2};"
                 :: "l"(&g_agg2s[d]), "f"(z.x), "f"(z.y) : "memory");
}

__global__ void k_final(const float* __restrict__ b2, float* __restrict__ out) {
    int n = blockIdx.x * blockDim.x + threadIdx.x;
    if (n >= N_NODES) return;
    float inv = g_inv[n];
    float2 a = g_agg2s[n];
    float2 r = g_zr[n];
    float v0 = a.x * inv + r.x + b2[0];
    float v1 = a.y * inv + r.y + b2[1];
    float s = 1.0f / fmaxf(sqrtf(v0 * v0 + v1 * v1), 1e-12f);
    v0 *= s; v1 *= s;
    float m = fmaxf(v0, v1);
    float l = m + logf(expf(v0 - m) + expf(v1 - m));
    out[(size_t)n * 2 + 0] = v0 - l;
    out[(size_t)n * 2 + 1] = v1 - l;
}

extern "C" void kernel_launch(void* const* d_in, const int* in_sizes, int n_in,
                              void* d_out, int out_size) {
    const float* x   = (const float*)d_in[0];
    const int*   ei  = (const int*)d_in[1];
    const float* W1l = (const float*)d_in[2];
    const float* b1  = (const float*)d_in[3];
    const float* W1r = (const float*)d_in[4];
    const float* W2l = (const float*)d_in[5];
    const float* b2  = (const float*)d_in[6];
    const float* W2r = (const float*)d_in[7];
    float*       out = (float*)d_out;

    int E = in_sizes[1] / 2;
    const int* src = ei;
    const int* dst = ei + E;

    cudaFuncSetAttribute(k_gemm, cudaFuncAttributeMaxDynamicSharedMemorySize, SMEM_DYN);

    k_zero<<<592, 256>>>();
    k_Wsplit<<<256, 256>>>(W1l, W1r);
    k_scatter1<<<(E * 32 + 255) / 256, 256>>>(x, src, dst, E);
    k_inv<<<(N_NODES + 255) / 256, 256>>>();
    k_conv<<<(N_NODES * 64 + 255) / 256, 256>>>(x);
    k_gemm<<<N_TILES, 512, SMEM_DYN>>>(b1, W2l, W2r);
    k_scatter2<<<(E + 255) / 256, 256>>>(src, dst, E);
    k_final<<<(N_NODES + 255) / 256, 256>>>(b2, out);
}

// round 7
// speedup vs baseline: 3.6830x; 1.1840x over previous
#include <cuda_runtime.h>
#include <cuda_bf16.h>
#include <math.h>
#include <stdint.h>

#define N_NODES 100000
#define IN_FEAT 128
#define HIDDEN  256
#define N_TILES 782

// ---------------- scratch (static device globals) ----------------
__device__ float  g_agg1[(size_t)N_NODES * IN_FEAT];    // 51.2 MB
__device__ float  g_cnt [N_NODES];
__device__ float2 g_zl  [N_NODES];
__device__ float2 g_zr  [N_NODES];
__device__ float2 g_agg2s[N_NODES];
__device__ __nv_bfloat16 g_Whi[256 * 256];              // B[n=256][k=256] (hi)
__device__ __nv_bfloat16 g_Wlo[256 * 256];              // lo

// ---------------- helpers ----------------
__device__ __forceinline__ uint32_t smem_u32(const void* p) {
    uint32_t a;
    asm("{ .reg .u64 t; cvta.to.shared.u64 t, %1; cvt.u32.u64 %0, t; }" : "=r"(a) : "l"(p));
    return a;
}
__device__ __forceinline__ void ldsm_x4(uint32_t* r, uint32_t addr) {
    asm volatile("ldmatrix.sync.aligned.m8n8.x4.shared.b16 {%0,%1,%2,%3}, [%4];"
                 : "=r"(r[0]), "=r"(r[1]), "=r"(r[2]), "=r"(r[3]) : "r"(addr));
}
__device__ __forceinline__ void mma_bf16(float* d, const uint32_t* a, uint32_t b0, uint32_t b1) {
    asm volatile("mma.sync.aligned.m16n8k16.row.col.f32.bf16.bf16.f32 "
                 "{%0,%1,%2,%3}, {%4,%5,%6,%7}, {%8,%9}, {%0,%1,%2,%3};"
                 : "+f"(d[0]), "+f"(d[1]), "+f"(d[2]), "+f"(d[3])
                 : "r"(a[0]), "r"(a[1]), "r"(a[2]), "r"(a[3]), "r"(b0), "r"(b1));
}
__device__ __forceinline__ void cp16(uint32_t sm, const void* g) {
    asm volatile("cp.async.cg.shared.global [%0], [%1], 16;" :: "r"(sm), "l"(g));
}
#define CP_COMMIT() asm volatile("cp.async.commit_group;" ::: "memory")
#define CP_WAIT0()  asm volatile("cp.async.wait_group 0;" ::: "memory")

// SMEM layout (dynamic), 80B-padded rows; double-buffered stages
#define AH_OFF(st)  ((st) * 20480u)                     // 128*80
#define AL_OFF(st)  ((st) * 20480u + 10240u)
#define BH_OFF(st)  (40960u + (st) * 40960u)            // 256*80
#define BL_OFF(st)  (40960u + (st) * 40960u + 20480u)
#define OFF_W2   122880u   // 4*256 f32
#define OFF_B1   126976u   // 256 f32
#define OFF_NORM 128000u   // 128 f32
#define OFF_Z    128512u   // 128*4 f32
#define OFF_INV  130560u   // 128 f32
#define SMEM_DYN 131072

// ---------------- small kernels ----------------
__global__ void k_zero() {
    const size_t n1 = (size_t)N_NODES * IN_FEAT;
    size_t stride = (size_t)gridDim.x * blockDim.x;
    size_t i0 = (size_t)blockIdx.x * blockDim.x + threadIdx.x;
    float4 z4 = make_float4(0.f, 0.f, 0.f, 0.f);
    for (size_t i = i0; i < n1 / 4; i += stride) ((float4*)g_agg1)[i] = z4;
    for (size_t i = i0; i < N_NODES; i += stride) {
        g_cnt[i] = 0.0f;
        g_agg2s[i] = make_float2(0.f, 0.f);
    }
}

__global__ void k_Wsplit(const float* __restrict__ W1l, const float* __restrict__ W1r) {
    int idx = blockIdx.x * blockDim.x + threadIdx.x;   // 0..65535
    if (idx >= 256 * 256) return;
    int h = idx >> 8, k = idx & 255;
    float v = (k < 128) ? W1l[h * 128 + k] : W1r[h * 128 + (k - 128)];
    __nv_bfloat16 hi = __float2bfloat16(v);
    __nv_bfloat16 lo = __float2bfloat16(v - __bfloat162float(hi));
    g_Whi[idx] = hi;
    g_Wlo[idx] = lo;
}

__global__ void k_scatter1(const float* __restrict__ x,
                           const int* __restrict__ src,
                           const int* __restrict__ dst, int E) {
    int gw   = (blockIdx.x * blockDim.x + threadIdx.x) >> 5;
    int lane = threadIdx.x & 31;
    if (gw >= E) return;
    int s = src[gw];
    int d = dst[gw];
    float4 v = ((const float4*)(x + (size_t)s * IN_FEAT))[lane];
    float* o = g_agg1 + (size_t)d * IN_FEAT + lane * 4;
    asm volatile("red.global.add.v4.f32 [%0], {%1, %2, %3, %4};"
                 :: "l"(o), "f"(v.x), "f"(v.y), "f"(v.z), "f"(v.w) : "memory");
    if (lane == 0)
        asm volatile("red.global.add.f32 [%0], %1;"
                     :: "l"(&g_cnt[d]), "f"(1.0f) : "memory");
}

// ---------------- HMMA GEMM, fused A conversion + double buffering ----------------
// acc = Ahi@Whi^T + Ahi@Wlo^T + Alo@Whi^T;  A built in-kernel from [agg1*inv | x] fp32.
// epilogue: +b1, l2norm, relu, project onto W2 -> zl/zr
__global__ void __launch_bounds__(512, 1) k_gemm(const float* __restrict__ x,
                                                 const float* __restrict__ b1,
                                                 const float* __restrict__ W2l,
                                                 const float* __restrict__ W2r) {
    extern __shared__ char smem[];
    const int t    = threadIdx.x;
    const int lane = t & 31;
    const int wid  = t >> 5;
    const int wm   = wid >> 2;        // 0..3 (m strip of 32)
    const int wn   = wid & 3;         // 0..3 (n strip of 64)
    const int n0   = blockIdx.x * 128;

    float* sW2   = (float*)(smem + OFF_W2);
    float* sB1   = (float*)(smem + OFF_B1);
    float* sNorm = (float*)(smem + OFF_NORM);
    float* sZ    = (float*)(smem + OFF_Z);
    float* sInv  = (float*)(smem + OFF_INV);

    for (int i = t; i < 256; i += 512) sB1[i] = b1[i];
    for (int i = t; i < 1024; i += 512) {
        int m = i >> 8, k = i & 255;
        sW2[i] = (m < 2) ? W2l[m * 256 + k] : W2r[(m - 2) * 256 + k];
    }
    if (t < 128) {
        int n = n0 + t;
        sInv[t] = (n < N_NODES) ? (1.0f / fmaxf(g_cnt[n], 1.0f)) : 0.0f;
        sNorm[t] = 0.f;
        ((float4*)sZ)[t] = make_float4(0.f, 0.f, 0.f, 0.f);
    }
    __syncthreads();   // sInv visible before A conversion

    const uint32_t smb  = smem_u32(smem);
    const uint32_t rowo = (lane & 7) + ((lane >> 3) & 1) * 8;  // ldmatrix row offset
    const uint32_t kB   = (lane >> 4) * 16;                    // ldmatrix k-byte offset

    float acc[2][8][4];
#pragma unroll
    for (int a = 0; a < 2; a++)
#pragma unroll
        for (int b = 0; b < 8; b++)
#pragma unroll
            for (int c = 0; c < 4; c++) acc[a][b][c] = 0.f;

    // per-thread A-load geometry: 2 float4 per stage
    const int arow = t >> 3;          // 0..63?? no: idx below
    (void)arow;

    float4 av[2];

    // ---- A fp32 load into regs for chunk kc ----
    auto loadA = [&](int kc) {
#pragma unroll
        for (int i = 0; i < 2; i++) {
            int idx = t + i * 512;        // 0..1023
            int row = idx >> 3;           // 0..127
            int c4  = (idx & 7) * 4;      // 0,4,...,28
            int n   = n0 + row;
            float4 v = make_float4(0.f, 0.f, 0.f, 0.f);
            if (n < N_NODES) {
                if (kc < 128) {
                    v = *(const float4*)(g_agg1 + (size_t)n * 128 + kc + c4);
                    float iv = sInv[row];
                    v.x *= iv; v.y *= iv; v.z *= iv; v.w *= iv;
                } else {
                    v = *(const float4*)(x + (size_t)n * 128 + (kc - 128) + c4);
                }
            }
            av[i] = v;
        }
    };
    // ---- convert + STS A regs into stage ----
    auto stsA = [&](int st) {
#pragma unroll
        for (int i = 0; i < 2; i++) {
            int idx = t + i * 512;
            int row = idx >> 3;
            int c4  = (idx & 7) * 4;
            float4 v = av[i];
            __nv_bfloat16 h0 = __float2bfloat16(v.x), h1 = __float2bfloat16(v.y);
            __nv_bfloat16 h2 = __float2bfloat16(v.z), h3 = __float2bfloat16(v.w);
            __nv_bfloat16 l0 = __float2bfloat16(v.x - __bfloat162float(h0));
            __nv_bfloat16 l1 = __float2bfloat16(v.y - __bfloat162float(h1));
            __nv_bfloat16 l2 = __float2bfloat16(v.z - __bfloat162float(h2));
            __nv_bfloat16 l3 = __float2bfloat16(v.w - __bfloat162float(h3));
            uint32_t base = row * 80 + c4 * 2;
            __nv_bfloat162* ph = (__nv_bfloat162*)(smem + AH_OFF(st) + base);
            ph[0] = __halves2bfloat162(h0, h1);
            ph[1] = __halves2bfloat162(h2, h3);
            __nv_bfloat162* pl = (__nv_bfloat162*)(smem + AL_OFF(st) + base);
            pl[0] = __halves2bfloat162(l0, l1);
            pl[1] = __halves2bfloat162(l2, l3);
        }
    };
    // ---- cp.async B chunk into stage ----
    auto issueB = [&](int kc, int st) {
#pragma unroll
        for (int i = 0; i < 2; i++) {
            int idx = t + i * 512;        // 0..1023
            int br = idx >> 2, bc = idx & 3;
            uint32_t doff = (uint32_t)(br * 80 + bc * 16);
            const __nv_bfloat16* sh = g_Whi + (size_t)br * 256 + kc + bc * 8;
            const __nv_bfloat16* sl = g_Wlo + (size_t)br * 256 + kc + bc * 8;
            cp16(smb + BH_OFF(st) + doff, sh);
            cp16(smb + BL_OFF(st) + doff, sl);
        }
    };
    // ---- MMA compute on stage ----
    auto compute = [&](int st) {
#pragma unroll
        for (int s = 0; s < 2; s++) {
            uint32_t ah[2][4], al[2][4];
#pragma unroll
            for (int tm = 0; tm < 2; tm++) {
                uint32_t r = (wm * 32 + tm * 16 + rowo) * 80 + s * 32 + kB;
                ldsm_x4(ah[tm], smb + AH_OFF(st) + r);
                ldsm_x4(al[tm], smb + AL_OFF(st) + r);
            }
#pragma unroll
            for (int tp = 0; tp < 4; tp++) {
                uint32_t br = (wn * 64 + tp * 16 + rowo) * 80 + s * 32 + kB;
                uint32_t bh[4], bl[4];
                ldsm_x4(bh, smb + BH_OFF(st) + br);
                ldsm_x4(bl, smb + BL_OFF(st) + br);
#pragma unroll
                for (int tm = 0; tm < 2; tm++) {
                    mma_bf16(acc[tm][2 * tp],     ah[tm], bh[0], bh[2]);
                    mma_bf16(acc[tm][2 * tp],     al[tm], bh[0], bh[2]);
                    mma_bf16(acc[tm][2 * tp],     ah[tm], bl[0], bl[2]);
                    mma_bf16(acc[tm][2 * tp + 1], ah[tm], bh[1], bh[3]);
                    mma_bf16(acc[tm][2 * tp + 1], al[tm], bh[1], bh[3]);
                    mma_bf16(acc[tm][2 * tp + 1], ah[tm], bl[1], bl[3]);
                }
            }
        }
    };

    // ---- prologue: stage 0 ----
    loadA(0);
    issueB(0, 0);
    CP_COMMIT();
    stsA(0);
    CP_WAIT0();
    __syncthreads();

    // ---- pipelined main loop: 8 chunks of K=32 ----
    for (int kci = 0; kci < 8; kci++) {
        int cur = kci & 1, nxt = cur ^ 1;
        if (kci < 7) {
            loadA((kci + 1) * 32);
            issueB((kci + 1) * 32, nxt);
            CP_COMMIT();
        }
        compute(cur);
        if (kci < 7) {
            stsA(nxt);
            CP_WAIT0();
        }
        __syncthreads();
    }

    // ---- epilogue ----
    // phase A: +bias, per-row sum of squares
#pragma unroll
    for (int tm = 0; tm < 2; tm++) {
        float s0 = 0.f, s1 = 0.f;
#pragma unroll
        for (int tn = 0; tn < 8; tn++) {
            int c0 = wn * 64 + tn * 8 + (lane & 3) * 2;
            float b0v = sB1[c0], b1v = sB1[c0 + 1];
            acc[tm][tn][0] += b0v;
            acc[tm][tn][1] += b1v;
            acc[tm][tn][2] += b0v;
            acc[tm][tn][3] += b1v;
            s0 += acc[tm][tn][0] * acc[tm][tn][0] + acc[tm][tn][1] * acc[tm][tn][1];
            s1 += acc[tm][tn][2] * acc[tm][tn][2] + acc[tm][tn][3] * acc[tm][tn][3];
        }
        s0 += __shfl_xor_sync(0xffffffffu, s0, 1);
        s0 += __shfl_xor_sync(0xffffffffu, s0, 2);
        s1 += __shfl_xor_sync(0xffffffffu, s1, 1);
        s1 += __shfl_xor_sync(0xffffffffu, s1, 2);
        if ((lane & 3) == 0) {
            int r = wm * 32 + tm * 16 + (lane >> 2);
            atomicAdd(&sNorm[r], s0);
            atomicAdd(&sNorm[r + 8], s1);
        }
    }
    __syncthreads();
    if (t < 128) sNorm[t] = 1.0f / fmaxf(sqrtf(sNorm[t]), 1e-12f);
    __syncthreads();

    // phase C: relu(norm), project onto W2 rows
#pragma unroll
    for (int tm = 0; tm < 2; tm++) {
        int rbase = wm * 32 + tm * 16 + (lane >> 2);
        float rc0 = sNorm[rbase], rc1 = sNorm[rbase + 8];
        float d0[4] = {0.f, 0.f, 0.f, 0.f};
        float d1[4] = {0.f, 0.f, 0.f, 0.f};
#pragma unroll
        for (int tn = 0; tn < 8; tn++) {
            int c0 = wn * 64 + tn * 8 + (lane & 3) * 2;
            float h00 = fmaxf(acc[tm][tn][0] * rc0, 0.f);
            float h01 = fmaxf(acc[tm][tn][1] * rc0, 0.f);
            float h10 = fmaxf(acc[tm][tn][2] * rc1, 0.f);
            float h11 = fmaxf(acc[tm][tn][3] * rc1, 0.f);
#pragma unroll
            for (int o = 0; o < 4; o++) {
                float w0 = sW2[o * 256 + c0], w1 = sW2[o * 256 + c0 + 1];
                d0[o] += h00 * w0 + h01 * w1;
                d1[o] += h10 * w0 + h11 * w1;
            }
        }
#pragma unroll
        for (int o = 0; o < 4; o++) {
            d0[o] += __shfl_xor_sync(0xffffffffu, d0[o], 1);
            d0[o] += __shfl_xor_sync(0xffffffffu, d0[o], 2);
            d1[o] += __shfl_xor_sync(0xffffffffu, d1[o], 1);
            d1[o] += __shfl_xor_sync(0xffffffffu, d1[o], 2);
        }
        if ((lane & 3) == 0) {
#pragma unroll
            for (int o = 0; o < 4; o++) {
                atomicAdd(&sZ[rbase * 4 + o], d0[o]);
                atomicAdd(&sZ[(rbase + 8) * 4 + o], d1[o]);
            }
        }
    }
    __syncthreads();
    if (t < 128) {
        int n = n0 + t;
        if (n < N_NODES) {
            g_zl[n] = make_float2(sZ[t * 4 + 0], sZ[t * 4 + 1]);
            g_zr[n] = make_float2(sZ[t * 4 + 2], sZ[t * 4 + 3]);
        }
    }
}

// ---------------- scatter layer 2 + final ----------------
__global__ void k_scatter2(const int* __restrict__ src,
                           const int* __restrict__ dst, int E) {
    int e = blockIdx.x * blockDim.x + threadIdx.x;
    if (e >= E) return;
    int s = src[e];
    int d = dst[e];
    float2 z = g_zl[s];
    asm volatile("red.global.add.v2.f32 [%0], {%1, %2};"
                 :: "l"(&g_agg2s[d]), "f"(z.x), "f"(z.y) : "memory");
}

__global__ void k_final(const float* __restrict__ b2, float* __restrict__ out) {
    int n = blockIdx.x * blockDim.x + threadIdx.x;
    if (n >= N_NODES) return;
    float inv = 1.0f / fmaxf(g_cnt[n], 1.0f);
    float2 a = g_agg2s[n];
    float2 r = g_zr[n];
    float v0 = a.x * inv + r.x + b2[0];
    float v1 = a.y * inv + r.y + b2[1];
    float s = 1.0f / fmaxf(sqrtf(v0 * v0 + v1 * v1), 1e-12f);
    v0 *= s; v1 *= s;
    float m = fmaxf(v0, v1);
    float l = m + logf(expf(v0 - m) + expf(v1 - m));
    out[(size_t)n * 2 + 0] = v0 - l;
    out[(size_t)n * 2 + 1] = v1 - l;
}

extern "C" void kernel_launch(void* const* d_in, const int* in_sizes, int n_in,
                              void* d_out, int out_size) {
    const float* x   = (const float*)d_in[0];
    const int*   ei  = (const int*)d_in[1];
    const float* W1l = (const float*)d_in[2];
    const float* b1  = (const float*)d_in[3];
    const float* W1r = (const float*)d_in[4];
    const float* W2l = (const float*)d_in[5];
    const float* b2  = (const float*)d_in[6];
    const float* W2r = (const float*)d_in[7];
    float*       out = (float*)d_out;

    int E = in_sizes[1] / 2;
    const int* src = ei;
    const int* dst = ei + E;

    cudaFuncSetAttribute(k_gemm, cudaFuncAttributeMaxDynamicSharedMemorySize, SMEM_DYN);

    k_zero<<<592, 256>>>();
    k_Wsplit<<<256, 256>>>(W1l, W1r);
    k_scatter1<<<(E * 32 + 255) / 256, 256>>>(x, src, dst, E);
    k_gemm<<<N_TILES, 512, SMEM_DYN>>>(x, b1, W2l, W2r);
    k_scatter2<<<(E + 255) / 256, 256>>>(src, dst, E);
    k_final<<<(N_NODES + 255) / 256, 256>>>(b2, out);
}

// round 8
// speedup vs baseline: 3.8561x; 1.0470x over previous
#include <cuda_runtime.h>
#include <cuda_bf16.h>
#include <math.h>
#include <stdint.h>

#define N_NODES 100000
#define IN_FEAT 128
#define HIDDEN  256
#define N_TILES 1563   // ceil(100000/64)

// ---------------- scratch (static device globals) ----------------
__device__ float  g_agg1[(size_t)N_NODES * IN_FEAT];    // 51.2 MB
__device__ float  g_cnt [N_NODES];
__device__ float2 g_zl  [N_NODES];
__device__ float2 g_zr  [N_NODES];
__device__ float2 g_agg2s[N_NODES];
__device__ __nv_bfloat16 g_Whi[256 * 256];              // B[n=256][k=256] (hi)
__device__ __nv_bfloat16 g_Wlo[256 * 256];              // lo

// ---------------- helpers ----------------
__device__ __forceinline__ uint32_t smem_u32(const void* p) {
    uint32_t a;
    asm("{ .reg .u64 t; cvta.to.shared.u64 t, %1; cvt.u32.u64 %0, t; }" : "=r"(a) : "l"(p));
    return a;
}
__device__ __forceinline__ void ldsm_x4(uint32_t* r, uint32_t addr) {
    asm volatile("ldmatrix.sync.aligned.m8n8.x4.shared.b16 {%0,%1,%2,%3}, [%4];"
                 : "=r"(r[0]), "=r"(r[1]), "=r"(r[2]), "=r"(r[3]) : "r"(addr));
}
__device__ __forceinline__ void mma_bf16(float* d, const uint32_t* a, uint32_t b0, uint32_t b1) {
    asm volatile("mma.sync.aligned.m16n8k16.row.col.f32.bf16.bf16.f32 "
                 "{%0,%1,%2,%3}, {%4,%5,%6,%7}, {%8,%9}, {%0,%1,%2,%3};"
                 : "+f"(d[0]), "+f"(d[1]), "+f"(d[2]), "+f"(d[3])
                 : "r"(a[0]), "r"(a[1]), "r"(a[2]), "r"(a[3]), "r"(b0), "r"(b1));
}
__device__ __forceinline__ void cp16(uint32_t sm, const void* g) {
    asm volatile("cp.async.cg.shared.global [%0], [%1], 16;" :: "r"(sm), "l"(g));
}
#define CP_COMMIT() asm volatile("cp.async.commit_group;" ::: "memory")
#define CP_WAIT0()  asm volatile("cp.async.wait_group 0;" ::: "memory")

// SMEM layout (dynamic), 80B-padded rows; double-buffered stages; M-tile=64
#define AH_OFF(st)  ((st) * 10240u)                     // 64*80
#define AL_OFF(st)  ((st) * 10240u + 5120u)
#define BH_OFF(st)  (20480u + (st) * 40960u)            // 256*80
#define BL_OFF(st)  (20480u + (st) * 40960u + 20480u)
#define OFF_W2   102400u   // 4*256 f32
#define OFF_B1   106496u   // 256 f32
#define OFF_NORM 107520u   // 64 f32
#define OFF_Z    107776u   // 64*4 f32
#define OFF_INV  108800u   // 64 f32
#define SMEM_DYN 109056

// ---------------- small kernels ----------------
__global__ void k_zero() {
    const size_t n1 = (size_t)N_NODES * IN_FEAT;
    size_t stride = (size_t)gridDim.x * blockDim.x;
    size_t i0 = (size_t)blockIdx.x * blockDim.x + threadIdx.x;
    float4 z4 = make_float4(0.f, 0.f, 0.f, 0.f);
    for (size_t i = i0; i < n1 / 4; i += stride) ((float4*)g_agg1)[i] = z4;
    for (size_t i = i0; i < N_NODES; i += stride) {
        g_cnt[i] = 0.0f;
        g_agg2s[i] = make_float2(0.f, 0.f);
    }
}

__global__ void k_Wsplit(const float* __restrict__ W1l, const float* __restrict__ W1r) {
    int idx = blockIdx.x * blockDim.x + threadIdx.x;   // 0..65535
    if (idx >= 256 * 256) return;
    int h = idx >> 8, k = idx & 255;
    float v = (k < 128) ? W1l[h * 128 + k] : W1r[h * 128 + (k - 128)];
    __nv_bfloat16 hi = __float2bfloat16(v);
    __nv_bfloat16 lo = __float2bfloat16(v - __bfloat162float(hi));
    g_Whi[idx] = hi;
    g_Wlo[idx] = lo;
}

__global__ void k_scatter1(const float* __restrict__ x,
                           const int* __restrict__ src,
                           const int* __restrict__ dst, int E) {
    int gw   = (blockIdx.x * blockDim.x + threadIdx.x) >> 5;
    int lane = threadIdx.x & 31;
    if (gw >= E) return;
    int s = src[gw];
    int d = dst[gw];
    float4 v = ((const float4*)(x + (size_t)s * IN_FEAT))[lane];
    float* o = g_agg1 + (size_t)d * IN_FEAT + lane * 4;
    asm volatile("red.global.add.v4.f32 [%0], {%1, %2, %3, %4};"
                 :: "l"(o), "f"(v.x), "f"(v.y), "f"(v.z), "f"(v.w) : "memory");
    if (lane == 0)
        asm volatile("red.global.add.f32 [%0], %1;"
                     :: "l"(&g_cnt[d]), "f"(1.0f) : "memory");
}

// ---------------- HMMA GEMM: tile M=64 x N=256, 256 thr, 2 CTAs/SM ----------------
// acc = Ahi@Whi^T + Ahi@Wlo^T + Alo@Whi^T;  A built in-kernel from [agg1*inv | x] fp32.
// epilogue: +b1, l2norm, relu, project onto W2 -> zl/zr
__global__ void __launch_bounds__(256, 2) k_gemm(const float* __restrict__ x,
                                                 const float* __restrict__ b1,
                                                 const float* __restrict__ W2l,
                                                 const float* __restrict__ W2r) {
    extern __shared__ char smem[];
    const int t    = threadIdx.x;
    const int lane = t & 31;
    const int wid  = t >> 5;
    const int wm   = wid >> 2;        // 0..1 (m strip of 32)
    const int wn   = wid & 3;         // 0..3 (n strip of 64)
    const int n0   = blockIdx.x * 64;

    float* sW2   = (float*)(smem + OFF_W2);
    float* sB1   = (float*)(smem + OFF_B1);
    float* sNorm = (float*)(smem + OFF_NORM);
    float* sZ    = (float*)(smem + OFF_Z);
    float* sInv  = (float*)(smem + OFF_INV);

    sB1[t] = b1[t];
    for (int i = t; i < 1024; i += 256) {
        int m = i >> 8, k = i & 255;
        sW2[i] = (m < 2) ? W2l[m * 256 + k] : W2r[(m - 2) * 256 + k];
    }
    if (t < 64) {
        int n = n0 + t;
        sInv[t] = (n < N_NODES) ? (1.0f / fmaxf(g_cnt[n], 1.0f)) : 0.0f;
        sNorm[t] = 0.f;
        ((float4*)sZ)[t] = make_float4(0.f, 0.f, 0.f, 0.f);
    }
    __syncthreads();   // sInv visible before A conversion

    const uint32_t smb  = smem_u32(smem);
    const uint32_t rowo = (lane & 7) + ((lane >> 3) & 1) * 8;  // ldmatrix row offset
    const uint32_t kB   = (lane >> 4) * 16;                    // ldmatrix k-byte offset

    float acc[2][8][4];
#pragma unroll
    for (int a = 0; a < 2; a++)
#pragma unroll
        for (int b = 0; b < 8; b++)
#pragma unroll
            for (int c = 0; c < 4; c++) acc[a][b][c] = 0.f;

    float4 av[2];

    // ---- A fp32 load into regs for chunk kc (64 rows x 32 cols) ----
    auto loadA = [&](int kc) {
#pragma unroll
        for (int i = 0; i < 2; i++) {
            int idx = t + i * 256;        // 0..511
            int row = idx >> 3;           // 0..63
            int c4  = (idx & 7) * 4;      // 0..28
            int n   = n0 + row;
            float4 v = make_float4(0.f, 0.f, 0.f, 0.f);
            if (n < N_NODES) {
                if (kc < 128) {
                    v = *(const float4*)(g_agg1 + (size_t)n * 128 + kc + c4);
                    float iv = sInv[row];
                    v.x *= iv; v.y *= iv; v.z *= iv; v.w *= iv;
                } else {
                    v = *(const float4*)(x + (size_t)n * 128 + (kc - 128) + c4);
                }
            }
            av[i] = v;
        }
    };
    // ---- convert + STS A regs into stage ----
    auto stsA = [&](int st) {
#pragma unroll
        for (int i = 0; i < 2; i++) {
            int idx = t + i * 256;
            int row = idx >> 3;
            int c4  = (idx & 7) * 4;
            float4 v = av[i];
            __nv_bfloat16 h0 = __float2bfloat16(v.x), h1 = __float2bfloat16(v.y);
            __nv_bfloat16 h2 = __float2bfloat16(v.z), h3 = __float2bfloat16(v.w);
            __nv_bfloat16 l0 = __float2bfloat16(v.x - __bfloat162float(h0));
            __nv_bfloat16 l1 = __float2bfloat16(v.y - __bfloat162float(h1));
            __nv_bfloat16 l2 = __float2bfloat16(v.z - __bfloat162float(h2));
            __nv_bfloat16 l3 = __float2bfloat16(v.w - __bfloat162float(h3));
            uint32_t base = row * 80 + c4 * 2;
            __nv_bfloat162* ph = (__nv_bfloat162*)(smem + AH_OFF(st) + base);
            ph[0] = __halves2bfloat162(h0, h1);
            ph[1] = __halves2bfloat162(h2, h3);
            __nv_bfloat162* pl = (__nv_bfloat162*)(smem + AL_OFF(st) + base);
            pl[0] = __halves2bfloat162(l0, l1);
            pl[1] = __halves2bfloat162(l2, l3);
        }
    };
    // ---- cp.async B chunk (256 rows x 32 cols, 2 splits) into stage ----
    auto issueB = [&](int kc, int st) {
#pragma unroll
        for (int i = 0; i < 4; i++) {
            int idx = t + i * 256;        // 0..1023
            int br = idx >> 2, bc = idx & 3;
            uint32_t doff = (uint32_t)(br * 80 + bc * 16);
            const __nv_bfloat16* sh = g_Whi + (size_t)br * 256 + kc + bc * 8;
            const __nv_bfloat16* sl = g_Wlo + (size_t)br * 256 + kc + bc * 8;
            cp16(smb + BH_OFF(st) + doff, sh);
            cp16(smb + BL_OFF(st) + doff, sl);
        }
    };
    // ---- MMA compute on stage ----
    auto compute = [&](int st) {
#pragma unroll
        for (int s = 0; s < 2; s++) {
            uint32_t ah[2][4], al[2][4];
#pragma unroll
            for (int tm = 0; tm < 2; tm++) {
                uint32_t r = (wm * 32 + tm * 16 + rowo) * 80 + s * 32 + kB;
                ldsm_x4(ah[tm], smb + AH_OFF(st) + r);
                ldsm_x4(al[tm], smb + AL_OFF(st) + r);
            }
#pragma unroll
            for (int tp = 0; tp < 4; tp++) {
                uint32_t br = (wn * 64 + tp * 16 + rowo) * 80 + s * 32 + kB;
                uint32_t bh[4], bl[4];
                ldsm_x4(bh, smb + BH_OFF(st) + br);
                ldsm_x4(bl, smb + BL_OFF(st) + br);
#pragma unroll
                for (int tm = 0; tm < 2; tm++) {
                    mma_bf16(acc[tm][2 * tp],     ah[tm], bh[0], bh[2]);
                    mma_bf16(acc[tm][2 * tp],     al[tm], bh[0], bh[2]);
                    mma_bf16(acc[tm][2 * tp],     ah[tm], bl[0], bl[2]);
                    mma_bf16(acc[tm][2 * tp + 1], ah[tm], bh[1], bh[3]);
                    mma_bf16(acc[tm][2 * tp + 1], al[tm], bh[1], bh[3]);
                    mma_bf16(acc[tm][2 * tp + 1], ah[tm], bl[1], bl[3]);
                }
            }
        }
    };

    // ---- prologue: stage 0 ----
    loadA(0);
    issueB(0, 0);
    CP_COMMIT();
    stsA(0);
    CP_WAIT0();
    __syncthreads();

    // ---- pipelined main loop: 8 chunks of K=32 ----
    for (int kci = 0; kci < 8; kci++) {
        int cur = kci & 1, nxt = cur ^ 1;
        if (kci < 7) {
            loadA((kci + 1) * 32);
            issueB((kci + 1) * 32, nxt);
            CP_COMMIT();
        }
        compute(cur);
        if (kci < 7) {
            stsA(nxt);
            CP_WAIT0();
        }
        __syncthreads();
    }

    // ---- epilogue ----
    // phase A: +bias, per-row sum of squares
#pragma unroll
    for (int tm = 0; tm < 2; tm++) {
        float s0 = 0.f, s1 = 0.f;
#pragma unroll
        for (int tn = 0; tn < 8; tn++) {
            int c0 = wn * 64 + tn * 8 + (lane & 3) * 2;
            float b0v = sB1[c0], b1v = sB1[c0 + 1];
            acc[tm][tn][0] += b0v;
            acc[tm][tn][1] += b1v;
            acc[tm][tn][2] += b0v;
            acc[tm][tn][3] += b1v;
            s0 += acc[tm][tn][0] * acc[tm][tn][0] + acc[tm][tn][1] * acc[tm][tn][1];
            s1 += acc[tm][tn][2] * acc[tm][tn][2] + acc[tm][tn][3] * acc[tm][tn][3];
        }
        s0 += __shfl_xor_sync(0xffffffffu, s0, 1);
        s0 += __shfl_xor_sync(0xffffffffu, s0, 2);
        s1 += __shfl_xor_sync(0xffffffffu, s1, 1);
        s1 += __shfl_xor_sync(0xffffffffu, s1, 2);
        if ((lane & 3) == 0) {
            int r = wm * 32 + tm * 16 + (lane >> 2);
            atomicAdd(&sNorm[r], s0);
            atomicAdd(&sNorm[r + 8], s1);
        }
    }
    __syncthreads();
    if (t < 64) sNorm[t] = 1.0f / fmaxf(sqrtf(sNorm[t]), 1e-12f);
    __syncthreads();

    // phase C: relu(norm), project onto W2 rows
#pragma unroll
    for (int tm = 0; tm < 2; tm++) {
        int rbase = wm * 32 + tm * 16 + (lane >> 2);
        float rc0 = sNorm[rbase], rc1 = sNorm[rbase + 8];
        float d0[4] = {0.f, 0.f, 0.f, 0.f};
        float d1[4] = {0.f, 0.f, 0.f, 0.f};
#pragma unroll
        for (int tn = 0; tn < 8; tn++) {
            int c0 = wn * 64 + tn * 8 + (lane & 3) * 2;
            float h00 = fmaxf(acc[tm][tn][0] * rc0, 0.f);
            float h01 = fmaxf(acc[tm][tn][1] * rc0, 0.f);
            float h10 = fmaxf(acc[tm][tn][2] * rc1, 0.f);
            float h11 = fmaxf(acc[tm][tn][3] * rc1, 0.f);
#pragma unroll
            for (int o = 0; o < 4; o++) {
                float w0 = sW2[o * 256 + c0], w1 = sW2[o * 256 + c0 + 1];
                d0[o] += h00 * w0 + h01 * w1;
                d1[o] += h10 * w0 + h11 * w1;
            }
        }
#pragma unroll
        for (int o = 0; o < 4; o++) {
            d0[o] += __shfl_xor_sync(0xffffffffu, d0[o], 1);
            d0[o] += __shfl_xor_sync(0xffffffffu, d0[o], 2);
            d1[o] += __shfl_xor_sync(0xffffffffu, d1[o], 1);
            d1[o] += __shfl_xor_sync(0xffffffffu, d1[o], 2);
        }
        if ((lane & 3) == 0) {
#pragma unroll
            for (int o = 0; o < 4; o++) {
                atomicAdd(&sZ[rbase * 4 + o], d0[o]);
                atomicAdd(&sZ[(rbase + 8) * 4 + o], d1[o]);
            }
        }
    }
    __syncthreads();
    if (t < 64) {
        int n = n0 + t;
        if (n < N_NODES) {
            g_zl[n] = make_float2(sZ[t * 4 + 0], sZ[t * 4 + 1]);
            g_zr[n] = make_float2(sZ[t * 4 + 2], sZ[t * 4 + 3]);
        }
    }
}

// ---------------- scatter layer 2 + final ----------------
__global__ void k_scatter2(const int* __restrict__ src,
                           const int* __restrict__ dst, int E) {
    int e = blockIdx.x * blockDim.x + threadIdx.x;
    if (e >= E) return;
    int s = src[e];
    int d = dst[e];
    float2 z = g_zl[s];
    asm volatile("red.global.add.v2.f32 [%0], {%1, %2};"
                 :: "l"(&g_agg2s[d]), "f"(z.x), "f"(z.y) : "memory");
}

__global__ void k_final(const float* __restrict__ b2, float* __restrict__ out) {
    int n = blockIdx.x * blockDim.x + threadIdx.x;
    if (n >= N_NODES) return;
    float inv = 1.0f / fmaxf(g_cnt[n], 1.0f);
    float2 a = g_agg2s[n];
    float2 r = g_zr[n];
    float v0 = a.x * inv + r.x + b2[0];
    float v1 = a.y * inv + r.y + b2[1];
    float s = 1.0f / fmaxf(sqrtf(v0 * v0 + v1 * v1), 1e-12f);
    v0 *= s; v1 *= s;
    float m = fmaxf(v0, v1);
    float l = m + logf(expf(v0 - m) + expf(v1 - m));
    out[(size_t)n * 2 + 0] = v0 - l;
    out[(size_t)n * 2 + 1] = v1 - l;
}

extern "C" void kernel_launch(void* const* d_in, const int* in_sizes, int n_in,
                              void* d_out, int out_size) {
    const float* x   = (const float*)d_in[0];
    const int*   ei  = (const int*)d_in[1];
    const float* W1l = (const float*)d_in[2];
    const float* b1  = (const float*)d_in[3];
    const float* W1r = (const float*)d_in[4];
    const float* W2l = (const float*)d_in[5];
    const float* b2  = (const float*)d_in[6];
    const float* W2r = (const float*)d_in[7];
    float*       out = (float*)d_out;

    int E = in_sizes[1] / 2;
    const int* src = ei;
    const int* dst = ei + E;

    cudaFuncSetAttribute(k_gemm, cudaFuncAttributeMaxDynamicSharedMemorySize, SMEM_DYN);

    k_zero<<<592, 256>>>();
    k_Wsplit<<<256, 256>>>(W1l, W1r);
    k_scatter1<<<(E * 32 + 255) / 256, 256>>>(x, src, dst, E);
    k_gemm<<<N_TILES, 256, SMEM_DYN>>>(x, b1, W2l, W2r);
    k_scatter2<<<(E + 255) / 256, 256>>>(src, dst, E);
    k_final<<<(N_NODES + 255) / 256, 256>>>(b2, out);
}

// round 9
// speedup vs baseline: 3.9530x; 1.0251x over previous
#include <cuda_runtime.h>
#include <cuda_bf16.h>
#include <math.h>
#include <stdint.h>

#define N_NODES 100000
#define IN_FEAT 128
#define HIDDEN  256
#define N_TILES 1563   // ceil(100000/64)

// ---------------- scratch (static device globals) ----------------
__device__ float  g_agg1[(size_t)N_NODES * IN_FEAT];    // 51.2 MB
__device__ float  g_cnt [N_NODES];
__device__ float2 g_zl  [N_NODES];
__device__ float2 g_zr  [N_NODES];
__device__ float2 g_agg2s[N_NODES];
__device__ __nv_bfloat16 g_Whi[256 * 256];              // B[n=256][k=256] (hi)
__device__ __nv_bfloat16 g_Wlo[256 * 256];              // lo

// ---------------- helpers ----------------
__device__ __forceinline__ uint32_t smem_u32(const void* p) {
    uint32_t a;
    asm("{ .reg .u64 t; cvta.to.shared.u64 t, %1; cvt.u32.u64 %0, t; }" : "=r"(a) : "l"(p));
    return a;
}
__device__ __forceinline__ void ldsm_x4(uint32_t* r, uint32_t addr) {
    asm volatile("ldmatrix.sync.aligned.m8n8.x4.shared.b16 {%0,%1,%2,%3}, [%4];"
                 : "=r"(r[0]), "=r"(r[1]), "=r"(r[2]), "=r"(r[3]) : "r"(addr));
}
__device__ __forceinline__ void mma_bf16(float* d, const uint32_t* a, uint32_t b0, uint32_t b1) {
    asm volatile("mma.sync.aligned.m16n8k16.row.col.f32.bf16.bf16.f32 "
                 "{%0,%1,%2,%3}, {%4,%5,%6,%7}, {%8,%9}, {%0,%1,%2,%3};"
                 : "+f"(d[0]), "+f"(d[1]), "+f"(d[2]), "+f"(d[3])
                 : "r"(a[0]), "r"(a[1]), "r"(a[2]), "r"(a[3]), "r"(b0), "r"(b1));
}
__device__ __forceinline__ void cp16(uint32_t sm, const void* g) {
    asm volatile("cp.async.cg.shared.global [%0], [%1], 16;" :: "r"(sm), "l"(g));
}
#define CP_COMMIT() asm volatile("cp.async.commit_group;" ::: "memory")
#define CP_WAIT0()  asm volatile("cp.async.wait_group 0;" ::: "memory")

// SMEM layout (dynamic), 80B-padded rows; double-buffered stages; M-tile=64
#define AH_OFF(st)  ((st) * 10240u)                     // 64*80
#define AL_OFF(st)  ((st) * 10240u + 5120u)
#define BH_OFF(st)  (20480u + (st) * 40960u)            // 256*80
#define BL_OFF(st)  (20480u + (st) * 40960u + 20480u)
#define OFF_W2   102400u   // 4*256 f32
#define OFF_B1   106496u   // 256 f32
#define OFF_NORM 107520u   // 64 f32
#define OFF_Z    107776u   // 64*4 f32
#define OFF_INV  108800u   // 64 f32
#define SMEM_DYN 109056

// ---------------- small kernels ----------------
__global__ void k_zero() {
    const size_t n1 = (size_t)N_NODES * IN_FEAT;
    size_t stride = (size_t)gridDim.x * blockDim.x;
    size_t i0 = (size_t)blockIdx.x * blockDim.x + threadIdx.x;
    float4 z4 = make_float4(0.f, 0.f, 0.f, 0.f);
    for (size_t i = i0; i < n1 / 4; i += stride) ((float4*)g_agg1)[i] = z4;
    for (size_t i = i0; i < N_NODES; i += stride) {
        g_cnt[i] = 0.0f;
        g_agg2s[i] = make_float2(0.f, 0.f);
    }
}

__global__ void k_Wsplit(const float* __restrict__ W1l, const float* __restrict__ W1r) {
    int idx = blockIdx.x * blockDim.x + threadIdx.x;   // 0..65535
    if (idx >= 256 * 256) return;
    int h = idx >> 8, k = idx & 255;
    float v = (k < 128) ? W1l[h * 128 + k] : W1r[h * 128 + (k - 128)];
    __nv_bfloat16 hi = __float2bfloat16(v);
    __nv_bfloat16 lo = __float2bfloat16(v - __bfloat162float(hi));
    g_Whi[idx] = hi;
    g_Wlo[idx] = lo;
}

__global__ void k_scatter1(const float* __restrict__ x,
                           const int* __restrict__ src,
                           const int* __restrict__ dst, int E) {
    int gw   = (blockIdx.x * blockDim.x + threadIdx.x) >> 5;
    int lane = threadIdx.x & 31;
    if (gw >= E) return;
    int s = src[gw];
    int d = dst[gw];
    float4 v = ((const float4*)(x + (size_t)s * IN_FEAT))[lane];
    float* o = g_agg1 + (size_t)d * IN_FEAT + lane * 4;
    asm volatile("red.global.add.v4.f32 [%0], {%1, %2, %3, %4};"
                 :: "l"(o), "f"(v.x), "f"(v.y), "f"(v.z), "f"(v.w) : "memory");
    if (lane == 0)
        asm volatile("red.global.add.f32 [%0], %1;"
                     :: "l"(&g_cnt[d]), "f"(1.0f) : "memory");
}

// ---------------- HMMA GEMM: tile M=64 x N=256, 256 thr, 2 CTAs/SM ----------------
__global__ void __launch_bounds__(256, 2) k_gemm(const float* __restrict__ x,
                                                 const float* __restrict__ b1,
                                                 const float* __restrict__ W2l,
                                                 const float* __restrict__ W2r) {
    extern __shared__ char smem[];
    const int t    = threadIdx.x;
    const int lane = t & 31;
    const int wid  = t >> 5;
    const int wm   = wid >> 2;        // 0..1 (m strip of 32)
    const int wn   = wid & 3;         // 0..3 (n strip of 64)
    const int n0   = blockIdx.x * 64;

    float* sW2   = (float*)(smem + OFF_W2);
    float* sB1   = (float*)(smem + OFF_B1);
    float* sNorm = (float*)(smem + OFF_NORM);
    float* sZ    = (float*)(smem + OFF_Z);
    float* sInv  = (float*)(smem + OFF_INV);

    sB1[t] = b1[t];
    for (int i = t; i < 1024; i += 256) {
        int m = i >> 8, k = i & 255;
        sW2[i] = (m < 2) ? W2l[m * 256 + k] : W2r[(m - 2) * 256 + k];
    }
    if (t < 64) {
        int n = n0 + t;
        sInv[t] = (n < N_NODES) ? (1.0f / fmaxf(g_cnt[n], 1.0f)) : 0.0f;
        sNorm[t] = 0.f;
        ((float4*)sZ)[t] = make_float4(0.f, 0.f, 0.f, 0.f);
    }
    __syncthreads();   // sInv visible before A conversion

    const uint32_t smb  = smem_u32(smem);
    const uint32_t rowo = (lane & 7) + ((lane >> 3) & 1) * 8;  // ldmatrix row offset
    const uint32_t kB   = (lane >> 4) * 16;                    // ldmatrix k-byte offset
    // hoisted per-warp ldsm bases (stage/k offsets folded as immediates after unroll)
    const uint32_t aBase = smb + (wm * 32 + rowo) * 80 + kB;
    const uint32_t bBase = smb + (wn * 64 + rowo) * 80 + kB;

    float acc[2][8][4];
#pragma unroll
    for (int a = 0; a < 2; a++)
#pragma unroll
        for (int b = 0; b < 8; b++)
#pragma unroll
            for (int c = 0; c < 4; c++) acc[a][b][c] = 0.f;

    // per-thread A-load geometry
    const int arow = t >> 3;             // 0..31 (+256 -> rows 32..63)
    const int ac4  = (t & 7) * 4;        // 0..28
    const int an0  = n0 + arow;
    const int an1  = n0 + arow + 32;
    const uint32_t asts = arow * 80 + ac4 * 2;

    float4 av[2];

    auto loadA = [&](int kc) {
#pragma unroll
        for (int i = 0; i < 2; i++) {
            int n = i ? an1 : an0;
            float4 v = make_float4(0.f, 0.f, 0.f, 0.f);
            if (n < N_NODES) {
                if (kc < 128) {
                    v = *(const float4*)(g_agg1 + (size_t)n * 128 + kc + ac4);
                    float iv = sInv[arow + i * 32];
                    v.x *= iv; v.y *= iv; v.z *= iv; v.w *= iv;
                } else {
                    v = *(const float4*)(x + (size_t)n * 128 + (kc - 128) + ac4);
                }
            }
            av[i] = v;
        }
    };
    auto stsA = [&](uint32_t ah_off, uint32_t al_off) {
#pragma unroll
        for (int i = 0; i < 2; i++) {
            float4 v = av[i];
            __nv_bfloat16 h0 = __float2bfloat16(v.x), h1 = __float2bfloat16(v.y);
            __nv_bfloat16 h2 = __float2bfloat16(v.z), h3 = __float2bfloat16(v.w);
            __nv_bfloat16 l0 = __float2bfloat16(v.x - __bfloat162float(h0));
            __nv_bfloat16 l1 = __float2bfloat16(v.y - __bfloat162float(h1));
            __nv_bfloat16 l2 = __float2bfloat16(v.z - __bfloat162float(h2));
            __nv_bfloat16 l3 = __float2bfloat16(v.w - __bfloat162float(h3));
            uint32_t base = asts + i * (32 * 80);
            __nv_bfloat162* ph = (__nv_bfloat162*)(smem + ah_off + base);
            ph[0] = __halves2bfloat162(h0, h1);
            ph[1] = __halves2bfloat162(h2, h3);
            __nv_bfloat162* pl = (__nv_bfloat162*)(smem + al_off + base);
            pl[0] = __halves2bfloat162(l0, l1);
            pl[1] = __halves2bfloat162(l2, l3);
        }
    };
    const int bbr = t >> 2;              // 0..63 (+64/128/192)
    const int bbc = t & 3;
    auto issueB = [&](int kc, uint32_t bh_off, uint32_t bl_off) {
#pragma unroll
        for (int i = 0; i < 4; i++) {
            int br = bbr + i * 64;
            uint32_t doff = (uint32_t)(br * 80 + bbc * 16);
            cp16(smb + bh_off + doff, g_Whi + (size_t)br * 256 + kc + bbc * 8);
            cp16(smb + bl_off + doff, g_Wlo + (size_t)br * 256 + kc + bbc * 8);
        }
    };
    auto compute = [&](uint32_t ah_off, uint32_t al_off, uint32_t bh_off, uint32_t bl_off) {
#pragma unroll
        for (int s = 0; s < 2; s++) {
            uint32_t ah[2][4], al[2][4];
#pragma unroll
            for (int tm = 0; tm < 2; tm++) {
                uint32_t r = aBase + tm * (16 * 80) + s * 32;
                ldsm_x4(ah[tm], r + ah_off);
                ldsm_x4(al[tm], r + al_off);
            }
#pragma unroll
            for (int tp = 0; tp < 4; tp++) {
                uint32_t br = bBase + tp * (16 * 80) + s * 32;
                uint32_t bh[4], bl[4];
                ldsm_x4(bh, br + bh_off);
                ldsm_x4(bl, br + bl_off);
#pragma unroll
                for (int tm = 0; tm < 2; tm++) {
                    // interleave the two accumulators: consecutive MMAs independent
                    mma_bf16(acc[tm][2 * tp],     ah[tm], bh[0], bh[2]);
                    mma_bf16(acc[tm][2 * tp + 1], ah[tm], bh[1], bh[3]);
                    mma_bf16(acc[tm][2 * tp],     al[tm], bh[0], bh[2]);
                    mma_bf16(acc[tm][2 * tp + 1], al[tm], bh[1], bh[3]);
                    mma_bf16(acc[tm][2 * tp],     ah[tm], bl[0], bl[2]);
                    mma_bf16(acc[tm][2 * tp + 1], ah[tm], bl[1], bl[3]);
                }
            }
        }
    };

    // ---- prologue: stage 0 ----
    loadA(0);
    issueB(0, BH_OFF(0), BL_OFF(0));
    CP_COMMIT();
    stsA(AH_OFF(0), AL_OFF(0));
    CP_WAIT0();
    __syncthreads();

    // ---- fully unrolled pipelined main loop: 8 chunks of K=32 ----
#pragma unroll
    for (int kci = 0; kci < 8; kci++) {
        const uint32_t cur = kci & 1, nxt = cur ^ 1;
        if (kci < 7) {
            loadA((kci + 1) * 32);
            issueB((kci + 1) * 32, BH_OFF(nxt), BL_OFF(nxt));
            CP_COMMIT();
        }
        compute(AH_OFF(cur), AL_OFF(cur), BH_OFF(cur), BL_OFF(cur));
        if (kci < 7) {
            stsA(AH_OFF(nxt), AL_OFF(nxt));
            CP_WAIT0();
        }
        __syncthreads();
    }

    // ---- epilogue ----
#pragma unroll
    for (int tm = 0; tm < 2; tm++) {
        float s0 = 0.f, s1 = 0.f;
#pragma unroll
        for (int tn = 0; tn < 8; tn++) {
            int c0 = wn * 64 + tn * 8 + (lane & 3) * 2;
            float b0v = sB1[c0], b1v = sB1[c0 + 1];
            acc[tm][tn][0] += b0v;
            acc[tm][tn][1] += b1v;
            acc[tm][tn][2] += b0v;
            acc[tm][tn][3] += b1v;
            s0 += acc[tm][tn][0] * acc[tm][tn][0] + acc[tm][tn][1] * acc[tm][tn][1];
            s1 += acc[tm][tn][2] * acc[tm][tn][2] + acc[tm][tn][3] * acc[tm][tn][3];
        }
        s0 += __shfl_xor_sync(0xffffffffu, s0, 1);
        s0 += __shfl_xor_sync(0xffffffffu, s0, 2);
        s1 += __shfl_xor_sync(0xffffffffu, s1, 1);
        s1 += __shfl_xor_sync(0xffffffffu, s1, 2);
        if ((lane & 3) == 0) {
            int r = wm * 32 + tm * 16 + (lane >> 2);
            atomicAdd(&sNorm[r], s0);
            atomicAdd(&sNorm[r + 8], s1);
        }
    }
    __syncthreads();
    if (t < 64) sNorm[t] = 1.0f / fmaxf(sqrtf(sNorm[t]), 1e-12f);
    __syncthreads();

#pragma unroll
    for (int tm = 0; tm < 2; tm++) {
        int rbase = wm * 32 + tm * 16 + (lane >> 2);
        float rc0 = sNorm[rbase], rc1 = sNorm[rbase + 8];
        float d0[4] = {0.f, 0.f, 0.f, 0.f};
        float d1[4] = {0.f, 0.f, 0.f, 0.f};
#pragma unroll
        for (int tn = 0; tn < 8; tn++) {
            int c0 = wn * 64 + tn * 8 + (lane & 3) * 2;
            float h00 = fmaxf(acc[tm][tn][0] * rc0, 0.f);
            float h01 = fmaxf(acc[tm][tn][1] * rc0, 0.f);
            float h10 = fmaxf(acc[tm][tn][2] * rc1, 0.f);
            float h11 = fmaxf(acc[tm][tn][3] * rc1, 0.f);
#pragma unroll
            for (int o = 0; o < 4; o++) {
                float w0 = sW2[o * 256 + c0], w1 = sW2[o * 256 + c0 + 1];
                d0[o] += h00 * w0 + h01 * w1;
                d1[o] += h10 * w0 + h11 * w1;
            }
        }
#pragma unroll
        for (int o = 0; o < 4; o++) {
            d0[o] += __shfl_xor_sync(0xffffffffu, d0[o], 1);
            d0[o] += __shfl_xor_sync(0xffffffffu, d0[o], 2);
            d1[o] += __shfl_xor_sync(0xffffffffu, d1[o], 1);
            d1[o] += __shfl_xor_sync(0xffffffffu, d1[o], 2);
        }
        if ((lane & 3) == 0) {
#pragma unroll
            for (int o = 0; o < 4; o++) {
                atomicAdd(&sZ[rbase * 4 + o], d0[o]);
                atomicAdd(&sZ[(rbase + 8) * 4 + o], d1[o]);
            }
        }
    }
    __syncthreads();
    if (t < 64) {
        int n = n0 + t;
        if (n < N_NODES) {
            g_zl[n] = make_float2(sZ[t * 4 + 0], sZ[t * 4 + 1]);
            g_zr[n] = make_float2(sZ[t * 4 + 2], sZ[t * 4 + 3]);
        }
    }
}

// ---------------- scatter layer 2 + final ----------------
__global__ void k_scatter2(const int* __restrict__ src,
                           const int* __restrict__ dst, int E) {
    int e = blockIdx.x * blockDim.x + threadIdx.x;
    if (e >= E) return;
    int s = src[e];
    int d = dst[e];
    float2 z = g_zl[s];
    asm volatile("red.global.add.v2.f32 [%0], {%1, %2};"
                 :: "l"(&g_agg2s[d]), "f"(z.x), "f"(z.y) : "memory");
}

__global__ void k_final(const float* __restrict__ b2, float* __restrict__ out) {
    int n = blockIdx.x * blockDim.x + threadIdx.x;
    if (n >= N_NODES) return;
    float inv = 1.0f / fmaxf(g_cnt[n], 1.0f);
    float2 a = g_agg2s[n];
    float2 r = g_zr[n];
    float v0 = a.x * inv + r.x + b2[0];
    float v1 = a.y * inv + r.y + b2[1];
    float s = 1.0f / fmaxf(sqrtf(v0 * v0 + v1 * v1), 1e-12f);
    v0 *= s; v1 *= s;
    float m = fmaxf(v0, v1);
    float l = m + logf(expf(v0 - m) + expf(v1 - m));
    out[(size_t)n * 2 + 0] = v0 - l;
    out[(size_t)n * 2 + 1] = v1 - l;
}

extern "C" void kernel_launch(void* const* d_in, const int* in_sizes, int n_in,
                              void* d_out, int out_size) {
    const float* x   = (const float*)d_in[0];
    const int*   ei  = (const int*)d_in[1];
    const float* W1l = (const float*)d_in[2];
    const float* b1  = (const float*)d_in[3];
    const float* W1r = (const float*)d_in[4];
    const float* W2l = (const float*)d_in[5];
    const float* b2  = (const float*)d_in[6];
    const float* W2r = (const float*)d_in[7];
    float*       out = (float*)d_out;

    int E = in_sizes[1] / 2;
    const int* src = ei;
    const int* dst = ei + E;

    cudaFuncSetAttribute(k_gemm, cudaFuncAttributeMaxDynamicSharedMemorySize, SMEM_DYN);

    k_zero<<<592, 256>>>();
    k_Wsplit<<<256, 256>>>(W1l, W1r);
    k_scatter1<<<(E * 32 + 255) / 256, 256>>>(x, src, dst, E);
    k_gemm<<<N_TILES, 256, SMEM_DYN>>>(x, b1, W2l, W2r);
    k_scatter2<<<(E + 255) / 256, 256>>>(src, dst, E);
    k_final<<<(N_NODES + 255) / 256, 256>>>(b2, out);
}

// round 10
// speedup vs baseline: 3.9726x; 1.0049x over previous
#include <cuda_runtime.h>
#include <cuda_bf16.h>
#include <math.h>
#include <stdint.h>

#define N_NODES 100000
#define IN_FEAT 128
#define HIDDEN  256
#define N_TILES 1563   // ceil(100000/64)

// ---------------- scratch (static device globals) ----------------
__device__ float  g_agg1[(size_t)N_NODES * IN_FEAT];    // 51.2 MB
__device__ float  g_cnt [N_NODES];
__device__ float2 g_zl  [N_NODES];
__device__ float2 g_zr  [N_NODES];
__device__ float2 g_agg2s[N_NODES];
__device__ __nv_bfloat16 g_Whi[256 * 256];              // B[n=256][k=256] (hi)
__device__ __nv_bfloat16 g_Wlo[256 * 256];              // lo

// ---------------- helpers ----------------
__device__ __forceinline__ uint32_t smem_u32(const void* p) {
    uint32_t a;
    asm("{ .reg .u64 t; cvta.to.shared.u64 t, %1; cvt.u32.u64 %0, t; }" : "=r"(a) : "l"(p));
    return a;
}
__device__ __forceinline__ void ldsm_x4(uint32_t* r, uint32_t addr) {
    asm volatile("ldmatrix.sync.aligned.m8n8.x4.shared.b16 {%0,%1,%2,%3}, [%4];"
                 : "=r"(r[0]), "=r"(r[1]), "=r"(r[2]), "=r"(r[3]) : "r"(addr));
}
__device__ __forceinline__ void mma_bf16(float* d, const uint32_t* a, uint32_t b0, uint32_t b1) {
    asm volatile("mma.sync.aligned.m16n8k16.row.col.f32.bf16.bf16.f32 "
                 "{%0,%1,%2,%3}, {%4,%5,%6,%7}, {%8,%9}, {%0,%1,%2,%3};"
                 : "+f"(d[0]), "+f"(d[1]), "+f"(d[2]), "+f"(d[3])
                 : "r"(a[0]), "r"(a[1]), "r"(a[2]), "r"(a[3]), "r"(b0), "r"(b1));
}
__device__ __forceinline__ void cp16(uint32_t sm, const void* g) {
    asm volatile("cp.async.cg.shared.global [%0], [%1], 16;" :: "r"(sm), "l"(g));
}
#define CP_COMMIT() asm volatile("cp.async.commit_group;" ::: "memory")
#define CP_WAIT0()  asm volatile("cp.async.wait_group 0;" ::: "memory")

// SMEM layout (dynamic), 80B-padded rows; double-buffered stages; M-tile=64
#define AH_OFF(st)  ((st) * 10240u)                     // 64*80
#define AL_OFF(st)  ((st) * 10240u + 5120u)
#define BH_OFF(st)  (20480u + (st) * 40960u)            // 256*80
#define BL_OFF(st)  (20480u + (st) * 40960u + 20480u)
#define OFF_W2   102400u   // 4*256 f32
#define OFF_B1   106496u   // 256 f32
#define OFF_NORM 107520u   // 64 f32
#define OFF_Z    107776u   // 64*4 f32
#define OFF_INV  108800u   // 64 f32
#define SMEM_DYN 109056

// ---------------- small kernels ----------------
__global__ void k_zero() {
    const size_t n1 = (size_t)N_NODES * IN_FEAT;
    size_t stride = (size_t)gridDim.x * blockDim.x;
    size_t i0 = (size_t)blockIdx.x * blockDim.x + threadIdx.x;
    float4 z4 = make_float4(0.f, 0.f, 0.f, 0.f);
    for (size_t i = i0; i < n1 / 4; i += stride) ((float4*)g_agg1)[i] = z4;
    for (size_t i = i0; i < N_NODES; i += stride) {
        g_cnt[i] = 0.0f;
        g_agg2s[i] = make_float2(0.f, 0.f);
    }
}

__global__ void k_Wsplit(const float* __restrict__ W1l, const float* __restrict__ W1r) {
    int idx = blockIdx.x * blockDim.x + threadIdx.x;   // 0..65535
    if (idx >= 256 * 256) return;
    int h = idx >> 8, k = idx & 255;
    float v = (k < 128) ? W1l[h * 128 + k] : W1r[h * 128 + (k - 128)];
    __nv_bfloat16 hi = __float2bfloat16(v);
    __nv_bfloat16 lo = __float2bfloat16(v - __bfloat162float(hi));
    g_Whi[idx] = hi;
    g_Wlo[idx] = lo;
}

__global__ void k_scatter1(const float* __restrict__ x,
                           const int* __restrict__ src,
                           const int* __restrict__ dst, int E) {
    int gw   = (blockIdx.x * blockDim.x + threadIdx.x) >> 5;
    int lane = threadIdx.x & 31;
    if (gw >= E) return;
    int s = src[gw];
    int d = dst[gw];
    float4 v = ((const float4*)(x + (size_t)s * IN_FEAT))[lane];
    float* o = g_agg1 + (size_t)d * IN_FEAT + lane * 4;
    asm volatile("red.global.add.v4.f32 [%0], {%1, %2, %3, %4};"
                 :: "l"(o), "f"(v.x), "f"(v.y), "f"(v.z), "f"(v.w) : "memory");
    if (lane == 0)
        asm volatile("red.global.add.f32 [%0], %1;"
                     :: "l"(&g_cnt[d]), "f"(1.0f) : "memory");
}

// ---------------- HMMA GEMM: tile M=64 x N=256, 256 thr, 2 CTAs/SM ----------------
__global__ void __launch_bounds__(256, 2) k_gemm(const float* __restrict__ x,
                                                 const float* __restrict__ b1,
                                                 const float* __restrict__ W2l,
                                                 const float* __restrict__ W2r) {
    extern __shared__ char smem[];
    const int t    = threadIdx.x;
    const int lane = t & 31;
    const int wid  = t >> 5;
    const int wm   = wid >> 2;        // 0..1 (m strip of 32)
    const int wn   = wid & 3;         // 0..3 (n strip of 64)
    const int n0   = blockIdx.x * 64;

    float* sW2   = (float*)(smem + OFF_W2);
    float* sB1   = (float*)(smem + OFF_B1);
    float* sNorm = (float*)(smem + OFF_NORM);
    float* sZ    = (float*)(smem + OFF_Z);
    float* sInv  = (float*)(smem + OFF_INV);

    sB1[t] = b1[t];
    for (int i = t; i < 1024; i += 256) {
        int m = i >> 8, k = i & 255;
        sW2[i] = (m < 2) ? W2l[m * 256 + k] : W2r[(m - 2) * 256 + k];
    }
    if (t < 64) {
        int n = n0 + t;
        sInv[t] = (n < N_NODES) ? (1.0f / fmaxf(g_cnt[n], 1.0f)) : 0.0f;
        sNorm[t] = 0.f;
        ((float4*)sZ)[t] = make_float4(0.f, 0.f, 0.f, 0.f);
    }
    __syncthreads();   // sInv visible before A conversion

    const uint32_t smb  = smem_u32(smem);
    const uint32_t rowo = (lane & 7) + ((lane >> 3) & 1) * 8;  // ldmatrix row offset
    const uint32_t kB   = (lane >> 4) * 16;                    // ldmatrix k-byte offset
    const uint32_t aBase = smb + (wm * 32 + rowo) * 80 + kB;
    const uint32_t bBase = smb + (wn * 64 + rowo) * 80 + kB;

    float acc[2][8][4];
#pragma unroll
    for (int a = 0; a < 2; a++)
#pragma unroll
        for (int b = 0; b < 8; b++)
#pragma unroll
            for (int c = 0; c < 4; c++) acc[a][b][c] = 0.f;

    // per-thread A-load geometry
    const int arow = t >> 3;             // 0..31 (+256 -> rows 32..63)
    const int ac4  = (t & 7) * 4;        // 0..28
    const int an0  = n0 + arow;
    const int an1  = n0 + arow + 32;
    const uint32_t asts = arow * 80 + ac4 * 2;

    float4 av[2];

    auto loadA = [&](int kc) {
#pragma unroll
        for (int i = 0; i < 2; i++) {
            int n = i ? an1 : an0;
            float4 v = make_float4(0.f, 0.f, 0.f, 0.f);
            if (n < N_NODES) {
                if (kc < 128) {
                    v = *(const float4*)(g_agg1 + (size_t)n * 128 + kc + ac4);
                    float iv = sInv[arow + i * 32];
                    v.x *= iv; v.y *= iv; v.z *= iv; v.w *= iv;
                } else {
                    v = *(const float4*)(x + (size_t)n * 128 + (kc - 128) + ac4);
                }
            }
            av[i] = v;
        }
    };
    auto stsA = [&](uint32_t ah_off, uint32_t al_off) {
#pragma unroll
        for (int i = 0; i < 2; i++) {
            float4 v = av[i];
            __nv_bfloat16 h0 = __float2bfloat16(v.x), h1 = __float2bfloat16(v.y);
            __nv_bfloat16 h2 = __float2bfloat16(v.z), h3 = __float2bfloat16(v.w);
            __nv_bfloat16 l0 = __float2bfloat16(v.x - __bfloat162float(h0));
            __nv_bfloat16 l1 = __float2bfloat16(v.y - __bfloat162float(h1));
            __nv_bfloat16 l2 = __float2bfloat16(v.z - __bfloat162float(h2));
            __nv_bfloat16 l3 = __float2bfloat16(v.w - __bfloat162float(h3));
            uint32_t base = asts + i * (32 * 80);
            __nv_bfloat162* ph = (__nv_bfloat162*)(smem + ah_off + base);
            ph[0] = __halves2bfloat162(h0, h1);
            ph[1] = __halves2bfloat162(h2, h3);
            __nv_bfloat162* pl = (__nv_bfloat162*)(smem + al_off + base);
            pl[0] = __halves2bfloat162(l0, l1);
            pl[1] = __halves2bfloat162(l2, l3);
        }
    };
    const int bbr = t >> 2;              // 0..63 (+64/128/192)
    const int bbc = t & 3;
    auto issueB = [&](int kc, uint32_t bh_off, uint32_t bl_off) {
#pragma unroll
        for (int i = 0; i < 4; i++) {
            int br = bbr + i * 64;
            uint32_t doff = (uint32_t)(br * 80 + bbc * 16);
            cp16(smb + bh_off + doff, g_Whi + (size_t)br * 256 + kc + bbc * 8);
            cp16(smb + bl_off + doff, g_Wlo + (size_t)br * 256 + kc + bbc * 8);
        }
    };
    // bulk-ldsm -> bulk-MMA: per k16 slice, load all fragments first, then stream
    // 48 MMAs round-robin over all 16 accumulator fragments (max independence).
    auto compute = [&](uint32_t ah_off, uint32_t al_off, uint32_t bh_off, uint32_t bl_off) {
#pragma unroll
        for (int s = 0; s < 2; s++) {
            const uint32_t so = s * 32;
            uint32_t ah[2][4], al[2][4];
            ldsm_x4(ah[0], aBase + so + ah_off);
            ldsm_x4(ah[1], aBase + 16 * 80 + so + ah_off);
            ldsm_x4(al[0], aBase + so + al_off);
            ldsm_x4(al[1], aBase + 16 * 80 + so + al_off);
            uint32_t bh[4][4];
#pragma unroll
            for (int tp = 0; tp < 4; tp++)
                ldsm_x4(bh[tp], bBase + tp * (16 * 80) + so + bh_off);

            // term hi*hi: 16 independent MMAs
#pragma unroll
            for (int tp = 0; tp < 4; tp++)
#pragma unroll
                for (int tm = 0; tm < 2; tm++) {
                    mma_bf16(acc[tm][2 * tp],     ah[tm], bh[tp][0], bh[tp][2]);
                    mma_bf16(acc[tm][2 * tp + 1], ah[tm], bh[tp][1], bh[tp][3]);
                }

            // load B-lo under cover of the lo*hi term
            uint32_t bl[4][4];
#pragma unroll
            for (int tp = 0; tp < 4; tp++)
                ldsm_x4(bl[tp], bBase + tp * (16 * 80) + so + bl_off);

            // term lo*hi
#pragma unroll
            for (int tp = 0; tp < 4; tp++)
#pragma unroll
                for (int tm = 0; tm < 2; tm++) {
                    mma_bf16(acc[tm][2 * tp],     al[tm], bh[tp][0], bh[tp][2]);
                    mma_bf16(acc[tm][2 * tp + 1], al[tm], bh[tp][1], bh[tp][3]);
                }
            // term hi*lo
#pragma unroll
            for (int tp = 0; tp < 4; tp++)
#pragma unroll
                for (int tm = 0; tm < 2; tm++) {
                    mma_bf16(acc[tm][2 * tp],     ah[tm], bl[tp][0], bl[tp][2]);
                    mma_bf16(acc[tm][2 * tp + 1], ah[tm], bl[tp][1], bl[tp][3]);
                }
        }
    };

    // ---- prologue: stage 0 ----
    loadA(0);
    issueB(0, BH_OFF(0), BL_OFF(0));
    CP_COMMIT();
    stsA(AH_OFF(0), AL_OFF(0));
    CP_WAIT0();
    __syncthreads();

    // ---- fully unrolled pipelined main loop: 8 chunks of K=32 ----
#pragma unroll
    for (int kci = 0; kci < 8; kci++) {
        const uint32_t cur = kci & 1, nxt = cur ^ 1;
        if (kci < 7) {
            loadA((kci + 1) * 32);
            issueB((kci + 1) * 32, BH_OFF(nxt), BL_OFF(nxt));
            CP_COMMIT();
        }
        compute(AH_OFF(cur), AL_OFF(cur), BH_OFF(cur), BL_OFF(cur));
        if (kci < 7) {
            stsA(AH_OFF(nxt), AL_OFF(nxt));
            CP_WAIT0();
        }
        __syncthreads();
    }

    // ---- epilogue ----
#pragma unroll
    for (int tm = 0; tm < 2; tm++) {
        float s0 = 0.f, s1 = 0.f;
#pragma unroll
        for (int tn = 0; tn < 8; tn++) {
            int c0 = wn * 64 + tn * 8 + (lane & 3) * 2;
            float b0v = sB1[c0], b1v = sB1[c0 + 1];
            acc[tm][tn][0] += b0v;
            acc[tm][tn][1] += b1v;
            acc[tm][tn][2] += b0v;
            acc[tm][tn][3] += b1v;
            s0 += acc[tm][tn][0] * acc[tm][tn][0] + acc[tm][tn][1] * acc[tm][tn][1];
            s1 += acc[tm][tn][2] * acc[tm][tn][2] + acc[tm][tn][3] * acc[tm][tn][3];
        }
        s0 += __shfl_xor_sync(0xffffffffu, s0, 1);
        s0 += __shfl_xor_sync(0xffffffffu, s0, 2);
        s1 += __shfl_xor_sync(0xffffffffu, s1, 1);
        s1 += __shfl_xor_sync(0xffffffffu, s1, 2);
        if ((lane & 3) == 0) {
            int r = wm * 32 + tm * 16 + (lane >> 2);
            atomicAdd(&sNorm[r], s0);
            atomicAdd(&sNorm[r + 8], s1);
        }
    }
    __syncthreads();
    if (t < 64) sNorm[t] = 1.0f / fmaxf(sqrtf(sNorm[t]), 1e-12f);
    __syncthreads();

#pragma unroll
    for (int tm = 0; tm < 2; tm++) {
        int rbase = wm * 32 + tm * 16 + (lane >> 2);
        float rc0 = sNorm[rbase], rc1 = sNorm[rbase + 8];
        float d0[4] = {0.f, 0.f, 0.f, 0.f};
        float d1[4] = {0.f, 0.f, 0.f, 0.f};
#pragma unroll
        for (int tn = 0; tn < 8; tn++) {
            int c0 = wn * 64 + tn * 8 + (lane & 3) * 2;
            float h00 = fmaxf(acc[tm][tn][0] * rc0, 0.f);
            float h01 = fmaxf(acc[tm][tn][1] * rc0, 0.f);
            float h10 = fmaxf(acc[tm][tn][2] * rc1, 0.f);
            float h11 = fmaxf(acc[tm][tn][3] * rc1, 0.f);
#pragma unroll
            for (int o = 0; o < 4; o++) {
                float w0 = sW2[o * 256 + c0], w1 = sW2[o * 256 + c0 + 1];
                d0[o] += h00 * w0 + h01 * w1;
                d1[o] += h10 * w0 + h11 * w1;
            }
        }
#pragma unroll
        for (int o = 0; o < 4; o++) {
            d0[o] += __shfl_xor_sync(0xffffffffu, d0[o], 1);
            d0[o] += __shfl_xor_sync(0xffffffffu, d0[o], 2);
            d1[o] += __shfl_xor_sync(0xffffffffu, d1[o], 1);
            d1[o] += __shfl_xor_sync(0xffffffffu, d1[o], 2);
        }
        if ((lane & 3) == 0) {
#pragma unroll
            for (int o = 0; o < 4; o++) {
                atomicAdd(&sZ[rbase * 4 + o], d0[o]);
                atomicAdd(&sZ[(rbase + 8) * 4 + o], d1[o]);
            }
        }
    }
    __syncthreads();
    if (t < 64) {
        int n = n0 + t;
        if (n < N_NODES) {
            g_zl[n] = make_float2(sZ[t * 4 + 0], sZ[t * 4 + 1]);
            g_zr[n] = make_float2(sZ[t * 4 + 2], sZ[t * 4 + 3]);
        }
    }
}

// ---------------- scatter layer 2 + final ----------------
__global__ void k_scatter2(const int* __restrict__ src,
                           const int* __restrict__ dst, int E) {
    int e = blockIdx.x * blockDim.x + threadIdx.x;
    if (e >= E) return;
    int s = src[e];
    int d = dst[e];
    float2 z = g_zl[s];
    asm volatile("red.global.add.v2.f32 [%0], {%1, %2};"
                 :: "l"(&g_agg2s[d]), "f"(z.x), "f"(z.y) : "memory");
}

__global__ void k_final(const float* __restrict__ b2, float* __restrict__ out) {
    int n = blockIdx.x * blockDim.x + threadIdx.x;
    if (n >= N_NODES) return;
    float inv = 1.0f / fmaxf(g_cnt[n], 1.0f);
    float2 a = g_agg2s[n];
    float2 r = g_zr[n];
    float v0 = a.x * inv + r.x + b2[0];
    float v1 = a.y * inv + r.y + b2[1];
    float s = 1.0f / fmaxf(sqrtf(v0 * v0 + v1 * v1), 1e-12f);
    v0 *= s; v1 *= s;
    float m = fmaxf(v0, v1);
    float l = m + logf(expf(v0 - m) + expf(v1 - m));
    out[(size_t)n * 2 + 0] = v0 - l;
    out[(size_t)n * 2 + 1] = v1 - l;
}

extern "C" void kernel_launch(void* const* d_in, const int* in_sizes, int n_in,
                              void* d_out, int out_size) {
    const float* x   = (const float*)d_in[0];
    const int*   ei  = (const int*)d_in[1];
    const float* W1l = (const float*)d_in[2];
    const float* b1  = (const float*)d_in[3];
    const float* W1r = (const float*)d_in[4];
    const float* W2l = (const float*)d_in[5];
    const float* b2  = (const float*)d_in[6];
    const float* W2r = (const float*)d_in[7];
    float*       out = (float*)d_out;

    int E = in_sizes[1] / 2;
    const int* src = ei;
    const int* dst = ei + E;

    cudaFuncSetAttribute(k_gemm, cudaFuncAttributeMaxDynamicSharedMemorySize, SMEM_DYN);

    k_zero<<<592, 256>>>();
    k_Wsplit<<<256, 256>>>(W1l, W1r);
    k_scatter1<<<(E * 32 + 255) / 256, 256>>>(x, src, dst, E);
    k_gemm<<<N_TILES, 256, SMEM_DYN>>>(x, b1, W2l, W2r);
    k_scatter2<<<(E + 255) / 256, 256>>>(src, dst, E);
    k_final<<<(N_NODES + 255) / 256, 256>>>(b2, out);
}